// round 1
// baseline (speedup 1.0000x reference)
#include <cuda_runtime.h>
#include <cuda_bf16.h>
#include <math.h>

// Problem constants
#define BB 4
#define TT 2048
#define CC 1024
#define HH 16
#define DD 64
#define MM (BB * TT)         // 8192
#define N_QKV (3 * CC)       // 3072
#define ATTN_SCALE 0.12f
#define RMS_EPS 1e-6f

// ---------------- device scratch (allocation-free) ----------------
__device__ float g_qkv[(size_t)MM * N_QKV];          // (M, 3C)
__device__ float g_q[(size_t)BB * HH * TT * DD];     // (B*H, T, D)
__device__ float g_k[(size_t)BB * HH * TT * DD];
__device__ float g_v[(size_t)BB * HH * TT * DD];
__device__ float g_y[(size_t)MM * CC];               // (M, C)

// =================================================================
// SGEMM  C = A * B^T,  A (M,K) row-major, B (N,K) row-major, C (M,N)
// Tile 128x128x16, 256 threads, 8x8 per thread (split-tile 4+4).
// =================================================================
__global__ __launch_bounds__(256, 2)
void sgemm_nt(const float* __restrict__ A, const float* __restrict__ B,
              float* __restrict__ C, int M, int N, int K)
{
    __shared__ float As[16 * 128];   // [k][m]
    __shared__ float Bs[16 * 128];   // [k][n]

    const int bm = blockIdx.y * 128;
    const int bn = blockIdx.x * 128;
    const int tid = threadIdx.x;
    const int tx = tid & 15;
    const int ty = tid >> 4;

    // loader mapping: each thread loads 2 float4 from A and 2 from B
    const int lr = tid & 127;            // row within tile
    const int lk = (tid >> 7) * 8;       // k-offset 0 or 8

    const float* Aptr = A + (size_t)(bm + lr) * K + lk;
    const float* Bptr = B + (size_t)(bn + lr) * K + lk;

    float acc[8][8];
#pragma unroll
    for (int i = 0; i < 8; i++)
#pragma unroll
        for (int j = 0; j < 8; j++) acc[i][j] = 0.0f;

    for (int k0 = 0; k0 < K; k0 += 16) {
#pragma unroll
        for (int u = 0; u < 2; u++) {
            float4 a4 = *(const float4*)(Aptr + k0 + 4 * u);
            As[(lk + 4 * u + 0) * 128 + lr] = a4.x;
            As[(lk + 4 * u + 1) * 128 + lr] = a4.y;
            As[(lk + 4 * u + 2) * 128 + lr] = a4.z;
            As[(lk + 4 * u + 3) * 128 + lr] = a4.w;
            float4 b4 = *(const float4*)(Bptr + k0 + 4 * u);
            Bs[(lk + 4 * u + 0) * 128 + lr] = b4.x;
            Bs[(lk + 4 * u + 1) * 128 + lr] = b4.y;
            Bs[(lk + 4 * u + 2) * 128 + lr] = b4.z;
            Bs[(lk + 4 * u + 3) * 128 + lr] = b4.w;
        }
        __syncthreads();

#pragma unroll
        for (int k = 0; k < 16; k++) {
            float a[8], b[8];
            *(float4*)&a[0] = *(const float4*)(As + k * 128 + (ty << 2));
            *(float4*)&a[4] = *(const float4*)(As + k * 128 + 64 + (ty << 2));
            *(float4*)&b[0] = *(const float4*)(Bs + k * 128 + (tx << 2));
            *(float4*)&b[4] = *(const float4*)(Bs + k * 128 + 64 + (tx << 2));
#pragma unroll
            for (int i = 0; i < 8; i++)
#pragma unroll
                for (int j = 0; j < 8; j++)
                    acc[i][j] += a[i] * b[j];
        }
        __syncthreads();
    }

#pragma unroll
    for (int i = 0; i < 8; i++) {
        int gr = bm + ((i < 4) ? ((ty << 2) + i) : (64 + (ty << 2) + i - 4));
        float* crow = C + (size_t)gr * N + bn;
        *(float4*)(crow + (tx << 2)) =
            make_float4(acc[i][0], acc[i][1], acc[i][2], acc[i][3]);
        *(float4*)(crow + 64 + (tx << 2)) =
            make_float4(acc[i][4], acc[i][5], acc[i][6], acc[i][7]);
    }
}

// =================================================================
// Post-process: v = l0*v + l1*ve ; rmsnorm(q), rmsnorm(k) ; rotary.
// One warp per (row m, head h). Lane l owns d=l and d=l+32.
// Outputs in (B*H, T, D) layout for attention.
// =================================================================
__global__ __launch_bounds__(256)
void postproc(const float* __restrict__ qkv, const float* __restrict__ ve,
              const float* __restrict__ lambdas,
              float* __restrict__ gq, float* __restrict__ gk, float* __restrict__ gv)
{
    const int pair = blockIdx.x * 8 + (threadIdx.x >> 5);  // 0 .. M*H-1
    const int l = threadIdx.x & 31;
    const int m = pair >> 4;        // row in (M)
    const int h = pair & 15;
    const int t = m & (TT - 1);
    const int b = m >> 11;          // m / T

    const float* row = qkv + (size_t)m * N_QKV + h * DD;
    float q0 = row[l],          q1 = row[l + 32];
    float k0 = row[CC + l],     k1 = row[CC + l + 32];
    float v0 = row[2 * CC + l], v1 = row[2 * CC + l + 32];

    const float lam0 = lambdas[0], lam1 = lambdas[1];
    const float* verow = ve + (size_t)m * CC + h * DD;
    v0 = lam0 * v0 + lam1 * verow[l];
    v1 = lam0 * v1 + lam1 * verow[l + 32];

    // rmsnorm over 64 elements (2 per lane)
    float sq = q0 * q0 + q1 * q1;
    float sk = k0 * k0 + k1 * k1;
#pragma unroll
    for (int o = 16; o; o >>= 1) {
        sq += __shfl_xor_sync(0xffffffffu, sq, o);
        sk += __shfl_xor_sync(0xffffffffu, sk, o);
    }
    float rq = 1.0f / sqrtf(sq * (1.0f / 64.0f) + RMS_EPS);
    float rk = 1.0f / sqrtf(sk * (1.0f / 64.0f) + RMS_EPS);
    q0 *= rq; q1 *= rq;
    k0 *= rk; k1 *= rk;

    // rotary: ang[l] = (1/1024)^(l/15) for l<16 else 0
    float ang = (l < 16) ? (float)exp2(-(10.0 / 15.0) * (double)l) : 0.0f;
    float th = (float)t * ang;
    float s, c;
    sincosf(th, &s, &c);
    float qa = q0 * c + q1 * s;
    float qb = q1 * c - q0 * s;
    float ka = k0 * c + k1 * s;
    float kb = k1 * c - k0 * s;

    size_t o = ((size_t)(b * HH + h) * TT + t) * DD + l;
    gq[o] = qa; gq[o + 32] = qb;
    gk[o] = ka; gk[o + 32] = kb;
    gv[o] = v0; gv[o + 32] = v1;
}

// =================================================================
// Flash attention (causal). Grid: (T/64, B*H). 256 threads.
// BQ=BKV=64. Thread (ty,tx) owns rows ty*4..+3, cols tx*4..+3.
// Dynamic smem: QsT[64][64] (d-major), KsT[64][64] (d-major),
//               Vs[64][64] (k-major), Ps[64][64] (r-major). 64 KB.
// =================================================================
__global__ __launch_bounds__(256, 2)
void flash_attn(const float* __restrict__ gq, const float* __restrict__ gk,
                const float* __restrict__ gv, float* __restrict__ gy)
{
    extern __shared__ float sm[];
    float* QsT = sm;             // [d][r]
    float* KsT = sm + 4096;      // [d][c]
    float* Vs  = sm + 8192;      // [k][d]
    float* Ps  = sm + 12288;     // [r][k]

    const int bh = blockIdx.y;          // 0..63
    const int qb = blockIdx.x;          // 0..31
    const int tid = threadIdx.x;
    const int tx = tid & 15;
    const int ty = tid >> 4;

    const size_t base = (size_t)bh * TT * DD;
    const float* Q = gq + base;
    const float* K = gk + base;
    const float* V = gv + base;

    // loader mapping for 64x64 tiles: thread -> row r, 16 d's starting c0
    const int r = tid & 63;
    const int c0 = (tid >> 6) << 4;     // 0,16,32,48

    // load Q tile transposed (d-major)
    {
        const float* qrow = Q + ((size_t)((qb << 6) + r) << 6) + c0;
#pragma unroll
        for (int u = 0; u < 4; u++) {
            float4 t4 = *(const float4*)(qrow + 4 * u);
            QsT[(c0 + 4 * u + 0) * 64 + r] = t4.x;
            QsT[(c0 + 4 * u + 1) * 64 + r] = t4.y;
            QsT[(c0 + 4 * u + 2) * 64 + r] = t4.z;
            QsT[(c0 + 4 * u + 3) * 64 + r] = t4.w;
        }
    }

    float mrow[4], lrow[4], Oacc[4][4];
#pragma unroll
    for (int i = 0; i < 4; i++) {
        mrow[i] = -1e30f;
        lrow[i] = 0.0f;
#pragma unroll
        for (int j = 0; j < 4; j++) Oacc[i][j] = 0.0f;
    }

    for (int kb = 0; kb <= qb; kb++) {
        // load K (transposed) and V (natural)
        {
            const float* krow = K + ((size_t)((kb << 6) + r) << 6) + c0;
            const float* vrow = V + ((size_t)((kb << 6) + r) << 6) + c0;
#pragma unroll
            for (int u = 0; u < 4; u++) {
                float4 t4 = *(const float4*)(krow + 4 * u);
                KsT[(c0 + 4 * u + 0) * 64 + r] = t4.x;
                KsT[(c0 + 4 * u + 1) * 64 + r] = t4.y;
                KsT[(c0 + 4 * u + 2) * 64 + r] = t4.z;
                KsT[(c0 + 4 * u + 3) * 64 + r] = t4.w;
                *(float4*)(Vs + r * 64 + c0 + 4 * u) = *(const float4*)(vrow + 4 * u);
            }
        }
        __syncthreads();

        // S = Q K^T (outer-product over d)
        float acc[4][4];
#pragma unroll
        for (int i = 0; i < 4; i++)
#pragma unroll
            for (int j = 0; j < 4; j++) acc[i][j] = 0.0f;

#pragma unroll 16
        for (int d = 0; d < 64; d++) {
            float4 a4 = *(const float4*)(QsT + d * 64 + (ty << 2));
            float4 b4 = *(const float4*)(KsT + d * 64 + (tx << 2));
            float a[4] = {a4.x, a4.y, a4.z, a4.w};
            float b[4] = {b4.x, b4.y, b4.z, b4.w};
#pragma unroll
            for (int i = 0; i < 4; i++)
#pragma unroll
                for (int j = 0; j < 4; j++)
                    acc[i][j] += a[i] * b[j];
        }

        // online softmax
        const bool diag = (kb == qb);
        const int qrow0 = (qb << 6) + (ty << 2);
        const int kcol0 = (kb << 6) + (tx << 2);
#pragma unroll
        for (int i = 0; i < 4; i++) {
            float s0[4];
#pragma unroll
            for (int j = 0; j < 4; j++) {
                float sv = acc[i][j] * ATTN_SCALE;
                if (diag && (kcol0 + j > qrow0 + i)) sv = -1e30f;
                s0[j] = sv;
            }
            float mx = fmaxf(fmaxf(s0[0], s0[1]), fmaxf(s0[2], s0[3]));
            mx = fmaxf(mx, __shfl_xor_sync(0xffffffffu, mx, 8));
            mx = fmaxf(mx, __shfl_xor_sync(0xffffffffu, mx, 4));
            mx = fmaxf(mx, __shfl_xor_sync(0xffffffffu, mx, 2));
            mx = fmaxf(mx, __shfl_xor_sync(0xffffffffu, mx, 1));
            float mnew = fmaxf(mrow[i], mx);
            float alpha = __expf(mrow[i] - mnew);
            mrow[i] = mnew;
            float p[4];
            float rs = 0.0f;
#pragma unroll
            for (int j = 0; j < 4; j++) {
                p[j] = __expf(s0[j] - mnew);
                rs += p[j];
            }
            *(float4*)(Ps + ((ty << 2) + i) * 64 + (tx << 2)) =
                make_float4(p[0], p[1], p[2], p[3]);
            rs += __shfl_xor_sync(0xffffffffu, rs, 8);
            rs += __shfl_xor_sync(0xffffffffu, rs, 4);
            rs += __shfl_xor_sync(0xffffffffu, rs, 2);
            rs += __shfl_xor_sync(0xffffffffu, rs, 1);
            lrow[i] = lrow[i] * alpha + rs;
#pragma unroll
            for (int j = 0; j < 4; j++) Oacc[i][j] *= alpha;
        }
        __syncthreads();

        // O += P V (dot-product over k, chunks of 4)
#pragma unroll 4
        for (int kc = 0; kc < 64; kc += 4) {
            float pa[4][4], vb[4][4];
#pragma unroll
            for (int i = 0; i < 4; i++) {
                float4 t4 = *(const float4*)(Ps + ((ty << 2) + i) * 64 + kc);
                pa[i][0] = t4.x; pa[i][1] = t4.y; pa[i][2] = t4.z; pa[i][3] = t4.w;
            }
#pragma unroll
            for (int kk = 0; kk < 4; kk++) {
                float4 t4 = *(const float4*)(Vs + (kc + kk) * 64 + (tx << 2));
                vb[kk][0] = t4.x; vb[kk][1] = t4.y; vb[kk][2] = t4.z; vb[kk][3] = t4.w;
            }
#pragma unroll
            for (int i = 0; i < 4; i++)
#pragma unroll
                for (int j = 0; j < 4; j++) {
                    Oacc[i][j] += pa[i][0] * vb[0][j];
                    Oacc[i][j] += pa[i][1] * vb[1][j];
                    Oacc[i][j] += pa[i][2] * vb[2][j];
                    Oacc[i][j] += pa[i][3] * vb[3][j];
                }
        }
        __syncthreads();
    }

    // epilogue: O /= l, scatter into (M, C) layout
    const int b = bh >> 4;
    const int h = bh & 15;
#pragma unroll
    for (int i = 0; i < 4; i++) {
        float inv = 1.0f / lrow[i];
        int t = (qb << 6) + (ty << 2) + i;
        float4 o4 = make_float4(Oacc[i][0] * inv, Oacc[i][1] * inv,
                                Oacc[i][2] * inv, Oacc[i][3] * inv);
        *(float4*)(gy + (size_t)(b * TT + t) * CC + h * DD + (tx << 2)) = o4;
    }
}

// =================================================================
// launch
// =================================================================
extern "C" void kernel_launch(void* const* d_in, const int* in_sizes, int n_in,
                              void* d_out, int out_size)
{
    const float* x       = (const float*)d_in[0];
    const float* ve      = (const float*)d_in[1];
    const float* qkv_w   = (const float*)d_in[2];
    const float* lambdas = (const float*)d_in[3];
    const float* c_proj_w = (const float*)d_in[4];
    float* out = (float*)d_out;

    float *qkv_p, *q_p, *k_p, *v_p, *y_p;
    cudaGetSymbolAddress((void**)&qkv_p, g_qkv);
    cudaGetSymbolAddress((void**)&q_p, g_q);
    cudaGetSymbolAddress((void**)&k_p, g_k);
    cudaGetSymbolAddress((void**)&v_p, g_v);
    cudaGetSymbolAddress((void**)&y_p, g_y);

    cudaFuncSetAttribute(flash_attn, cudaFuncAttributeMaxDynamicSharedMemorySize, 65536);

    // 1) qkv = x @ qkv_w^T
    sgemm_nt<<<dim3(N_QKV / 128, MM / 128), 256>>>(x, qkv_w, qkv_p, MM, N_QKV, CC);

    // 2) v-mix + rmsnorm + rotary, reshuffle into (B*H, T, D)
    postproc<<<(MM * HH) / 8, 256>>>(qkv_p, ve, lambdas, q_p, k_p, v_p);

    // 3) causal flash attention -> (M, C)
    flash_attn<<<dim3(TT / 64, BB * HH), 256, 65536>>>(q_p, k_p, v_p, y_p);

    // 4) out = y @ c_proj_w^T
    sgemm_nt<<<dim3(CC / 128, MM / 128), 256>>>(y_p, c_proj_w, out, MM, CC, CC);
}

// round 2
// speedup vs baseline: 1.0588x; 1.0588x over previous
#include <cuda_runtime.h>
#include <cuda_bf16.h>
#include <math.h>

// Problem constants
#define BB 4
#define TT 2048
#define CC 1024
#define HH 16
#define DD 64
#define MM (BB * TT)         // 8192
#define N_QKV (3 * CC)       // 3072
#define ATTN_SCALE 0.12f
#define RMS_EPS 1e-6f

// ---------------- device scratch (allocation-free) ----------------
__device__ float g_qkv[(size_t)MM * N_QKV];          // (M, 3C)
__device__ float g_q[(size_t)BB * HH * TT * DD];     // (B*H, T, D)
__device__ float g_k[(size_t)BB * HH * TT * DD];
__device__ float g_v[(size_t)BB * HH * TT * DD];
__device__ float g_y[(size_t)MM * CC];               // (M, C)

// =================================================================
// SGEMM  C = A * B^T,  A (M,K) row-major, B (N,K) row-major, C (M,N)
// Tile 128x128x16, 256 threads, 8x8 per thread (split-tile 4+4).
// =================================================================
__global__ __launch_bounds__(256, 2)
void sgemm_nt(const float* __restrict__ A, const float* __restrict__ B,
              float* __restrict__ C, int M, int N, int K)
{
    __shared__ float As[16 * 128];   // [k][m]
    __shared__ float Bs[16 * 128];   // [k][n]

    const int bm = blockIdx.y * 128;
    const int bn = blockIdx.x * 128;
    const int tid = threadIdx.x;
    const int tx = tid & 15;
    const int ty = tid >> 4;

    const int lr = tid & 127;            // row within tile
    const int lk = (tid >> 7) * 8;       // k-offset 0 or 8

    const float* Aptr = A + (size_t)(bm + lr) * K + lk;
    const float* Bptr = B + (size_t)(bn + lr) * K + lk;

    float acc[8][8];
#pragma unroll
    for (int i = 0; i < 8; i++)
#pragma unroll
        for (int j = 0; j < 8; j++) acc[i][j] = 0.0f;

    for (int k0 = 0; k0 < K; k0 += 16) {
#pragma unroll
        for (int u = 0; u < 2; u++) {
            float4 a4 = *(const float4*)(Aptr + k0 + 4 * u);
            As[(lk + 4 * u + 0) * 128 + lr] = a4.x;
            As[(lk + 4 * u + 1) * 128 + lr] = a4.y;
            As[(lk + 4 * u + 2) * 128 + lr] = a4.z;
            As[(lk + 4 * u + 3) * 128 + lr] = a4.w;
            float4 b4 = *(const float4*)(Bptr + k0 + 4 * u);
            Bs[(lk + 4 * u + 0) * 128 + lr] = b4.x;
            Bs[(lk + 4 * u + 1) * 128 + lr] = b4.y;
            Bs[(lk + 4 * u + 2) * 128 + lr] = b4.z;
            Bs[(lk + 4 * u + 3) * 128 + lr] = b4.w;
        }
        __syncthreads();

#pragma unroll
        for (int k = 0; k < 16; k++) {
            float a[8], b[8];
            *(float4*)&a[0] = *(const float4*)(As + k * 128 + (ty << 2));
            *(float4*)&a[4] = *(const float4*)(As + k * 128 + 64 + (ty << 2));
            *(float4*)&b[0] = *(const float4*)(Bs + k * 128 + (tx << 2));
            *(float4*)&b[4] = *(const float4*)(Bs + k * 128 + 64 + (tx << 2));
#pragma unroll
            for (int i = 0; i < 8; i++)
#pragma unroll
                for (int j = 0; j < 8; j++)
                    acc[i][j] += a[i] * b[j];
        }
        __syncthreads();
    }

#pragma unroll
    for (int i = 0; i < 8; i++) {
        int gr = bm + ((i < 4) ? ((ty << 2) + i) : (64 + (ty << 2) + i - 4));
        float* crow = C + (size_t)gr * N + bn;
        *(float4*)(crow + (tx << 2)) =
            make_float4(acc[i][0], acc[i][1], acc[i][2], acc[i][3]);
        *(float4*)(crow + 64 + (tx << 2)) =
            make_float4(acc[i][4], acc[i][5], acc[i][6], acc[i][7]);
    }
}

// =================================================================
// Post-process: v = l0*v + l1*ve ; rmsnorm(q), rmsnorm(k) ; rotary.
// One warp per (row m, head h). Lane l owns d=l and d=l+32.
// =================================================================
__global__ __launch_bounds__(256)
void postproc(const float* __restrict__ qkv, const float* __restrict__ ve,
              const float* __restrict__ lambdas,
              float* __restrict__ gq, float* __restrict__ gk, float* __restrict__ gv)
{
    const int pair = blockIdx.x * 8 + (threadIdx.x >> 5);  // 0 .. M*H-1
    const int l = threadIdx.x & 31;
    const int m = pair >> 4;        // row in (M)
    const int h = pair & 15;
    const int t = m & (TT - 1);
    const int b = m >> 11;          // m / T

    const float* row = qkv + (size_t)m * N_QKV + h * DD;
    float q0 = row[l],          q1 = row[l + 32];
    float k0 = row[CC + l],     k1 = row[CC + l + 32];
    float v0 = row[2 * CC + l], v1 = row[2 * CC + l + 32];

    const float lam0 = lambdas[0], lam1 = lambdas[1];
    const float* verow = ve + (size_t)m * CC + h * DD;
    v0 = lam0 * v0 + lam1 * verow[l];
    v1 = lam0 * v1 + lam1 * verow[l + 32];

    float sq = q0 * q0 + q1 * q1;
    float sk = k0 * k0 + k1 * k1;
#pragma unroll
    for (int o = 16; o; o >>= 1) {
        sq += __shfl_xor_sync(0xffffffffu, sq, o);
        sk += __shfl_xor_sync(0xffffffffu, sk, o);
    }
    float rq = 1.0f / sqrtf(sq * (1.0f / 64.0f) + RMS_EPS);
    float rk = 1.0f / sqrtf(sk * (1.0f / 64.0f) + RMS_EPS);
    q0 *= rq; q1 *= rq;
    k0 *= rk; k1 *= rk;

    float ang = (l < 16) ? (float)exp2(-(10.0 / 15.0) * (double)l) : 0.0f;
    float th = (float)t * ang;
    float s, c;
    sincosf(th, &s, &c);
    float qa = q0 * c + q1 * s;
    float qb = q1 * c - q0 * s;
    float ka = k0 * c + k1 * s;
    float kb = k1 * c - k0 * s;

    size_t o = ((size_t)(b * HH + h) * TT + t) * DD + l;
    gq[o] = qa; gq[o + 32] = qb;
    gk[o] = ka; gk[o + 32] = kb;
    gv[o] = v0; gv[o + 32] = v1;
}

// =================================================================
// Flash attention (causal), no-max softmax (scores bounded: |s|<=7.68
// since rms_norm gives ||q||=||k||=8, scale 0.12 => exp safe in fp32).
// Grid: (T/128, B*H). 256 threads. BQ=BKV=128.
// Smem (160KB): QsT[64][128] d-major, KsT[64][128] d-major,
//               Vs[128][64] k-major, Ps[128][128] k-major (swizzled).
// S phase: thread (ty,tx) owns rows ty*8..+7, cols tx*8..+7  (8x8).
// PV phase: thread owns rows ty*8..+7, d-cols tx*4..+3, full k (8x4).
// =================================================================
__global__ __launch_bounds__(256, 1)
void flash_attn(const float* __restrict__ gq, const float* __restrict__ gk,
                const float* __restrict__ gv, float* __restrict__ gy)
{
    extern __shared__ float sm[];
    float* QsT = sm;                 // 8192 floats
    float* KsT = sm + 8192;          // 8192
    float* Vs  = sm + 16384;         // 8192
    float* Ps  = sm + 24576;         // 16384

    const int bh = blockIdx.y;
    const int qb = (int)gridDim.x - 1 - (int)blockIdx.x;   // heavy tiles first
    const int tid = threadIdx.x;
    const int tx = tid & 15;
    const int ty = tid >> 4;

    const size_t base = (size_t)bh * TT * DD;
    const float* Q = gq + base;
    const float* K = gk + base;
    const float* V = gv + base;

    // loader mapping: 128 rows x 64 d; each thread: row lr, 32 d's from ld0
    const int lr = tid & 127;
    const int ld0 = (tid >> 7) << 5;     // 0 or 32

    // ---- load Q tile transposed (d-major) ----
    {
        const float* qrow = Q + ((size_t)((qb << 7) + lr) << 6) + ld0;
#pragma unroll
        for (int u = 0; u < 8; u++) {
            float4 t4 = *(const float4*)(qrow + 4 * u);
            QsT[(ld0 + 4 * u + 0) * 128 + lr] = t4.x;
            QsT[(ld0 + 4 * u + 1) * 128 + lr] = t4.y;
            QsT[(ld0 + 4 * u + 2) * 128 + lr] = t4.z;
            QsT[(ld0 + 4 * u + 3) * 128 + lr] = t4.w;
        }
    }

    float O[8][4];
    float lp[8];
#pragma unroll
    for (int i = 0; i < 8; i++) {
        lp[i] = 0.0f;
#pragma unroll
        for (int j = 0; j < 4; j++) O[i][j] = 0.0f;
    }

    for (int kb = 0; kb <= qb; kb++) {
        __syncthreads();   // previous PV reads of Ps/Vs done
        // ---- load K (transposed) + V (natural) ----
        {
            const float* krow = K + ((size_t)((kb << 7) + lr) << 6) + ld0;
            const float* vrow = V + ((size_t)((kb << 7) + lr) << 6) + ld0;
#pragma unroll
            for (int u = 0; u < 8; u++) {
                float4 t4 = *(const float4*)(krow + 4 * u);
                KsT[(ld0 + 4 * u + 0) * 128 + lr] = t4.x;
                KsT[(ld0 + 4 * u + 1) * 128 + lr] = t4.y;
                KsT[(ld0 + 4 * u + 2) * 128 + lr] = t4.z;
                KsT[(ld0 + 4 * u + 3) * 128 + lr] = t4.w;
                *(float4*)(Vs + lr * 64 + ld0 + 4 * u) = *(const float4*)(vrow + 4 * u);
            }
        }
        __syncthreads();

        // ---- S = Q K^T  (8x8 per thread, outer product over d) ----
        float acc[8][8];
#pragma unroll
        for (int i = 0; i < 8; i++)
#pragma unroll
            for (int j = 0; j < 8; j++) acc[i][j] = 0.0f;

#pragma unroll 4
        for (int d = 0; d < 64; d++) {
            float a[8], b[8];
            *(float4*)&a[0] = *(const float4*)(QsT + d * 128 + ty * 8);
            *(float4*)&a[4] = *(const float4*)(QsT + d * 128 + ty * 8 + 4);
            *(float4*)&b[0] = *(const float4*)(KsT + d * 128 + tx * 8);
            *(float4*)&b[4] = *(const float4*)(KsT + d * 128 + tx * 8 + 4);
#pragma unroll
            for (int i = 0; i < 8; i++)
#pragma unroll
                for (int j = 0; j < 8; j++)
                    acc[i][j] += a[i] * b[j];
        }

        // ---- exp (no max needed), accumulate partial row sums ----
        const bool diag = (kb == qb);
#pragma unroll
        for (int i = 0; i < 8; i++) {
            const int row = ty * 8 + i;
#pragma unroll
            for (int j = 0; j < 8; j++) {
                float s = acc[i][j] * ATTN_SCALE;
                float p = (diag && (tx * 8 + j > row)) ? 0.0f : __expf(s);
                acc[i][j] = p;
                lp[i] += p;
            }
        }

        // ---- write P k-major with XOR chunk swizzle ----
#pragma unroll
        for (int j = 0; j < 8; j++) {
            const int k = tx * 8 + j;
            float* dst = Ps + k * 128 + ((ty ^ tx) << 3);   // tx == k>>3
            *(float4*)dst = make_float4(acc[0][j], acc[1][j], acc[2][j], acc[3][j]);
            *(float4*)(dst + 4) = make_float4(acc[4][j], acc[5][j], acc[6][j], acc[7][j]);
        }
        __syncthreads();

        // ---- O += P V  (8x4 per thread, outer product over k) ----
#pragma unroll 4
        for (int k = 0; k < 128; k++) {
            float p[8], v[4];
            const float* pp = Ps + k * 128 + ((ty ^ (k >> 3)) << 3);
            *(float4*)&p[0] = *(const float4*)pp;
            *(float4*)&p[4] = *(const float4*)(pp + 4);
            *(float4*)&v[0] = *(const float4*)(Vs + k * 64 + tx * 4);
#pragma unroll
            for (int i = 0; i < 8; i++)
#pragma unroll
                for (int j = 0; j < 4; j++)
                    O[i][j] += p[i] * v[j];
        }
    }

    // ---- reduce row sums across the 16 tx threads ----
#pragma unroll
    for (int i = 0; i < 8; i++) {
        float s = lp[i];
        s += __shfl_xor_sync(0xffffffffu, s, 1);
        s += __shfl_xor_sync(0xffffffffu, s, 2);
        s += __shfl_xor_sync(0xffffffffu, s, 4);
        s += __shfl_xor_sync(0xffffffffu, s, 8);
        lp[i] = 1.0f / s;
    }

    // ---- epilogue: O/l, scatter into (M, C) layout ----
    const int b = bh >> 4;
    const int h = bh & 15;
#pragma unroll
    for (int i = 0; i < 8; i++) {
        const int t = (qb << 7) + ty * 8 + i;
        float4 o4 = make_float4(O[i][0] * lp[i], O[i][1] * lp[i],
                                O[i][2] * lp[i], O[i][3] * lp[i]);
        *(float4*)(gy + (size_t)(b * TT + t) * CC + h * DD + tx * 4) = o4;
    }
}

// =================================================================
// launch
// =================================================================
extern "C" void kernel_launch(void* const* d_in, const int* in_sizes, int n_in,
                              void* d_out, int out_size)
{
    const float* x        = (const float*)d_in[0];
    const float* ve       = (const float*)d_in[1];
    const float* qkv_w    = (const float*)d_in[2];
    const float* lambdas  = (const float*)d_in[3];
    const float* c_proj_w = (const float*)d_in[4];
    float* out = (float*)d_out;

    float *qkv_p, *q_p, *k_p, *v_p, *y_p;
    cudaGetSymbolAddress((void**)&qkv_p, g_qkv);
    cudaGetSymbolAddress((void**)&q_p, g_q);
    cudaGetSymbolAddress((void**)&k_p, g_k);
    cudaGetSymbolAddress((void**)&v_p, g_v);
    cudaGetSymbolAddress((void**)&y_p, g_y);

    cudaFuncSetAttribute(flash_attn, cudaFuncAttributeMaxDynamicSharedMemorySize, 163840);

    // 1) qkv = x @ qkv_w^T
    sgemm_nt<<<dim3(N_QKV / 128, MM / 128), 256>>>(x, qkv_w, qkv_p, MM, N_QKV, CC);

    // 2) v-mix + rmsnorm + rotary, reshuffle into (B*H, T, D)
    postproc<<<(MM * HH) / 8, 256>>>(qkv_p, ve, lambdas, q_p, k_p, v_p);

    // 3) causal flash attention -> (M, C)
    flash_attn<<<dim3(TT / 128, BB * HH), 256, 163840>>>(q_p, k_p, v_p, y_p);

    // 4) out = y @ c_proj_w^T
    sgemm_nt<<<dim3(CC / 128, MM / 128), 256>>>(y_p, c_proj_w, out, MM, CC, CC);
}

// round 4
// speedup vs baseline: 1.0752x; 1.0155x over previous
#include <cuda_runtime.h>
#include <cuda_bf16.h>
#include <math.h>

// Problem constants
#define BB 4
#define TT 2048
#define CC 1024
#define HH 16
#define DD 64
#define MM (BB * TT)         // 8192
#define N_QKV (3 * CC)       // 3072
#define ATTN_SCALE 0.12f
#define RMS_EPS 1e-6f

typedef unsigned long long ull;

// packed f32x2 fma: d = a*b + c elementwise on (lo,hi) pairs
#define FMA2(d, a, b, c) \
    asm("fma.rn.f32x2 %0, %1, %2, %3;" : "=l"(d) : "l"(a), "l"(b), "l"(c))
#define PACK2(d, x) \
    asm("mov.b64 %0, {%1, %1};" : "=l"(d) : "f"(x))
#define UNPACK2(lo, hi, v) \
    asm("mov.b64 {%0, %1}, %2;" : "=f"(lo), "=f"(hi) : "l"(v))

// ---------------- device scratch (allocation-free) ----------------
__device__ float g_qkv[(size_t)MM * N_QKV];          // (M, 3C)
__device__ float g_q[(size_t)BB * HH * TT * DD];     // (B*H, T, D)
__device__ float g_k[(size_t)BB * HH * TT * DD];
__device__ float g_v[(size_t)BB * HH * TT * DD];
__device__ float g_y[(size_t)MM * CC];               // (M, C)

// =================================================================
// SGEMM  C = A * B^T,  A (M,K) row-major, B (N,K) row-major, C (M,N)
// Tile 128x128x16, 256 threads, 8x8 per thread via packed f32x2.
// =================================================================
__global__ __launch_bounds__(256, 2)
void sgemm_nt(const float* __restrict__ A, const float* __restrict__ B,
              float* __restrict__ C, int M, int N, int K)
{
    __shared__ float As[16 * 128];   // [k][m]
    __shared__ float Bs[16 * 128];   // [k][n]

    const int bm = blockIdx.y * 128;
    const int bn = blockIdx.x * 128;
    const int tid = threadIdx.x;
    const int tx = tid & 15;
    const int ty = tid >> 4;

    const int lr = tid & 127;            // row within tile
    const int lk = (tid >> 7) * 8;       // k-offset 0 or 8

    const float* Aptr = A + (size_t)(bm + lr) * K + lk;
    const float* Bptr = B + (size_t)(bn + lr) * K + lk;

    ull acc2[8][4];
#pragma unroll
    for (int i = 0; i < 8; i++)
#pragma unroll
        for (int j = 0; j < 4; j++) acc2[i][j] = 0ull;

    for (int k0 = 0; k0 < K; k0 += 16) {
#pragma unroll
        for (int u = 0; u < 2; u++) {
            float4 a4 = *(const float4*)(Aptr + k0 + 4 * u);
            As[(lk + 4 * u + 0) * 128 + lr] = a4.x;
            As[(lk + 4 * u + 1) * 128 + lr] = a4.y;
            As[(lk + 4 * u + 2) * 128 + lr] = a4.z;
            As[(lk + 4 * u + 3) * 128 + lr] = a4.w;
            float4 b4 = *(const float4*)(Bptr + k0 + 4 * u);
            Bs[(lk + 4 * u + 0) * 128 + lr] = b4.x;
            Bs[(lk + 4 * u + 1) * 128 + lr] = b4.y;
            Bs[(lk + 4 * u + 2) * 128 + lr] = b4.z;
            Bs[(lk + 4 * u + 3) * 128 + lr] = b4.w;
        }
        __syncthreads();

#pragma unroll
        for (int k = 0; k < 16; k++) {
            float a[8];
            *(float4*)&a[0] = *(const float4*)(As + k * 128 + (ty << 2));
            *(float4*)&a[4] = *(const float4*)(As + k * 128 + 64 + (ty << 2));
            ull b2[4];
            b2[0] = *(const ull*)(Bs + k * 128 + (tx << 2));
            b2[1] = *(const ull*)(Bs + k * 128 + (tx << 2) + 2);
            b2[2] = *(const ull*)(Bs + k * 128 + 64 + (tx << 2));
            b2[3] = *(const ull*)(Bs + k * 128 + 64 + (tx << 2) + 2);
            ull aa[8];
#pragma unroll
            for (int i = 0; i < 8; i++) PACK2(aa[i], a[i]);
#pragma unroll
            for (int i = 0; i < 8; i++)
#pragma unroll
                for (int j = 0; j < 4; j++)
                    FMA2(acc2[i][j], aa[i], b2[j], acc2[i][j]);
        }
        __syncthreads();
    }

#pragma unroll
    for (int i = 0; i < 8; i++) {
        int gr = bm + ((i < 4) ? ((ty << 2) + i) : (64 + (ty << 2) + i - 4));
        float* crow = C + (size_t)gr * N + bn;
        float c0, c1, c2, c3;
        UNPACK2(c0, c1, acc2[i][0]);
        UNPACK2(c2, c3, acc2[i][1]);
        *(float4*)(crow + (tx << 2)) = make_float4(c0, c1, c2, c3);
        UNPACK2(c0, c1, acc2[i][2]);
        UNPACK2(c2, c3, acc2[i][3]);
        *(float4*)(crow + 64 + (tx << 2)) = make_float4(c0, c1, c2, c3);
    }
}

// =================================================================
// Post-process: v = l0*v + l1*ve ; rmsnorm(q), rmsnorm(k) ; rotary.
// One warp per (row m, head h). Lane l owns d=l and d=l+32.
// =================================================================
__global__ __launch_bounds__(256)
void postproc(const float* __restrict__ qkv, const float* __restrict__ ve,
              const float* __restrict__ lambdas,
              float* __restrict__ gq, float* __restrict__ gk, float* __restrict__ gv)
{
    const int pair = blockIdx.x * 8 + (threadIdx.x >> 5);  // 0 .. M*H-1
    const int l = threadIdx.x & 31;
    const int m = pair >> 4;        // row in (M)
    const int h = pair & 15;
    const int t = m & (TT - 1);
    const int b = m >> 11;          // m / T

    const float* row = qkv + (size_t)m * N_QKV + h * DD;
    float q0 = row[l],          q1 = row[l + 32];
    float k0 = row[CC + l],     k1 = row[CC + l + 32];
    float v0 = row[2 * CC + l], v1 = row[2 * CC + l + 32];

    const float lam0 = lambdas[0], lam1 = lambdas[1];
    const float* verow = ve + (size_t)m * CC + h * DD;
    v0 = lam0 * v0 + lam1 * verow[l];
    v1 = lam0 * v1 + lam1 * verow[l + 32];

    float sq = q0 * q0 + q1 * q1;
    float sk = k0 * k0 + k1 * k1;
#pragma unroll
    for (int o = 16; o; o >>= 1) {
        sq += __shfl_xor_sync(0xffffffffu, sq, o);
        sk += __shfl_xor_sync(0xffffffffu, sk, o);
    }
    float rq = 1.0f / sqrtf(sq * (1.0f / 64.0f) + RMS_EPS);
    float rk = 1.0f / sqrtf(sk * (1.0f / 64.0f) + RMS_EPS);
    q0 *= rq; q1 *= rq;
    k0 *= rk; k1 *= rk;

    float ang = (l < 16) ? (float)exp2(-(10.0 / 15.0) * (double)l) : 0.0f;
    float th = (float)t * ang;
    float s, c;
    sincosf(th, &s, &c);
    float qa = q0 * c + q1 * s;
    float qb = q1 * c - q0 * s;
    float ka = k0 * c + k1 * s;
    float kb = k1 * c - k0 * s;

    size_t o = ((size_t)(b * HH + h) * TT + t) * DD + l;
    gq[o] = qa; gq[o + 32] = qb;
    gk[o] = ka; gk[o + 32] = kb;
    gv[o] = v0; gv[o + 32] = v1;
}

// =================================================================
// Flash attention (causal), no-max softmax (|s| <= 7.68 since
// rms_norm gives ||q||=||k||=8, scale 0.12 => exp safe in fp32).
// Grid: (T/128, B*H). 256 threads. BQ=128, BKV=64.
// Smem (97KB, 2 CTAs/SM): QsT[64][128] d-major, KsT[64][64] d-major,
//   Vs[64][68] k-major (padded), Ps[64][128] k-major (chunk-swizzled).
// S phase: thread (ty,tx) owns rows ty*8..+7, cols tx*4..+3 (8x4).
// PV phase: thread owns rows ty*8..+7, d-cols tx*4..+3, full k (8x4).
// Inner loops use packed fma.rn.f32x2.
// =================================================================
#define VS_STRIDE 68

__global__ __launch_bounds__(256, 2)
void flash_attn(const float* __restrict__ gq, const float* __restrict__ gk,
                const float* __restrict__ gv, float* __restrict__ gy)
{
    extern __shared__ float sm[];
    float* QsT = sm;                         // 8192 floats (32KB)
    float* KsT = sm + 8192;                  // 4096 floats (16KB)
    float* Vs  = sm + 8192 + 4096;           // 64*68 = 4352 floats (17KB)
    float* Ps  = sm + 8192 + 4096 + 4352;    // 8192 floats (32KB)

    const int bh = blockIdx.y;
    const int qb = (int)gridDim.x - 1 - (int)blockIdx.x;   // heavy tiles first
    const int tid = threadIdx.x;
    const int tx = tid & 15;
    const int ty = tid >> 4;

    const size_t base = (size_t)bh * TT * DD;
    const float* Q = gq + base;
    const float* K = gk + base;
    const float* V = gv + base;

    // ---- load Q tile transposed (d-major): 128 rows x 64 d ----
    {
        const int r = tid & 127;
        const int d0 = (tid >> 7) << 5;      // 0 or 32
        const float* qrow = Q + ((size_t)((qb << 7) + r) << 6) + d0;
#pragma unroll
        for (int u = 0; u < 8; u++) {
            float4 t4 = *(const float4*)(qrow + 4 * u);
            QsT[(d0 + 4 * u + 0) * 128 + r] = t4.x;
            QsT[(d0 + 4 * u + 1) * 128 + r] = t4.y;
            QsT[(d0 + 4 * u + 2) * 128 + r] = t4.z;
            QsT[(d0 + 4 * u + 3) * 128 + r] = t4.w;
        }
    }

    ull O2[8][2];
    float lp[8];
#pragma unroll
    for (int i = 0; i < 8; i++) {
        lp[i] = 0.0f;
        O2[i][0] = 0ull; O2[i][1] = 0ull;
    }

    // KV loader mapping: 64 rows x 64 d
    const int kvr = tid & 63;
    const int kvd0 = (tid >> 6) << 4;        // 0,16,32,48

    const int nkb = 2 * qb + 2;              // kv tiles of 64
    for (int kb = 0; kb < nkb; kb++) {
        __syncthreads();   // previous PV/S reads of KsT/Vs/Ps done
        // ---- load K (transposed) + V (natural, padded stride) ----
        {
            const float* krow = K + ((size_t)((kb << 6) + kvr) << 6) + kvd0;
            const float* vrow = V + ((size_t)((kb << 6) + kvr) << 6) + kvd0;
#pragma unroll
            for (int u = 0; u < 4; u++) {
                float4 t4 = *(const float4*)(krow + 4 * u);
                KsT[(kvd0 + 4 * u + 0) * 64 + kvr] = t4.x;
                KsT[(kvd0 + 4 * u + 1) * 64 + kvr] = t4.y;
                KsT[(kvd0 + 4 * u + 2) * 64 + kvr] = t4.z;
                KsT[(kvd0 + 4 * u + 3) * 64 + kvr] = t4.w;
                *(float4*)(Vs + kvr * VS_STRIDE + kvd0 + 4 * u) =
                    *(const float4*)(vrow + 4 * u);
            }
        }
        __syncthreads();

        // ---- S = Q K^T  (8x4 per thread, packed over the 4 cols) ----
        ull sacc[8][2];
#pragma unroll
        for (int i = 0; i < 8; i++) { sacc[i][0] = 0ull; sacc[i][1] = 0ull; }

#pragma unroll 2
        for (int d = 0; d < 64; d++) {
            float a[8];
            *(float4*)&a[0] = *(const float4*)(QsT + d * 128 + ty * 8);
            *(float4*)&a[4] = *(const float4*)(QsT + d * 128 + ty * 8 + 4);
            ull b2[2];
            b2[0] = *(const ull*)(KsT + d * 64 + tx * 4);
            b2[1] = *(const ull*)(KsT + d * 64 + tx * 4 + 2);
            ull aa[8];
#pragma unroll
            for (int i = 0; i < 8; i++) PACK2(aa[i], a[i]);
#pragma unroll
            for (int i = 0; i < 8; i++) {
                FMA2(sacc[i][0], aa[i], b2[0], sacc[i][0]);
                FMA2(sacc[i][1], aa[i], b2[1], sacc[i][1]);
            }
        }

        // ---- exp (no running max), accumulate row-sum partials,
        //      write P k-major with chunk swizzle ----
        const bool diag = (kb >= 2 * qb);
        const int grow0 = (qb << 7) + ty * 8;
#pragma unroll
        for (int jj = 0; jj < 2; jj++) {
            float pc[8][2];
#pragma unroll
            for (int i = 0; i < 8; i++) {
                float s0, s1;
                UNPACK2(s0, s1, sacc[i][jj]);
                const int col = (kb << 6) + tx * 4 + jj * 2;
                const int grow = grow0 + i;
                float p0 = (diag && (col > grow)) ? 0.0f : __expf(s0 * ATTN_SCALE);
                float p1 = (diag && (col + 1 > grow)) ? 0.0f : __expf(s1 * ATTN_SCALE);
                pc[i][0] = p0; pc[i][1] = p1;
                lp[i] += p0 + p1;
            }
#pragma unroll
            for (int h2 = 0; h2 < 2; h2++) {
                const int k = tx * 4 + jj * 2 + h2;
                float* dst = Ps + k * 128 + ((ty ^ tx) << 3);
                *(float4*)dst = make_float4(pc[0][h2], pc[1][h2], pc[2][h2], pc[3][h2]);
                *(float4*)(dst + 4) = make_float4(pc[4][h2], pc[5][h2], pc[6][h2], pc[7][h2]);
            }
        }
        __syncthreads();

        // ---- O += P V  (8x4 per thread, packed over d pairs) ----
#pragma unroll 2
        for (int k = 0; k < 64; k++) {
            float p[8];
            const float* pp = Ps + k * 128 + ((ty ^ (k >> 2)) << 3);
            *(float4*)&p[0] = *(const float4*)pp;
            *(float4*)&p[4] = *(const float4*)(pp + 4);
            ull v2[2];
            v2[0] = *(const ull*)(Vs + k * VS_STRIDE + tx * 4);
            v2[1] = *(const ull*)(Vs + k * VS_STRIDE + tx * 4 + 2);
            ull pk[8];
#pragma unroll
            for (int i = 0; i < 8; i++) PACK2(pk[i], p[i]);
#pragma unroll
            for (int i = 0; i < 8; i++) {
                FMA2(O2[i][0], pk[i], v2[0], O2[i][0]);
                FMA2(O2[i][1], pk[i], v2[1], O2[i][1]);
            }
        }
    }

    // ---- reduce row sums across the 16 tx lanes ----
#pragma unroll
    for (int i = 0; i < 8; i++) {
        float s = lp[i];
        s += __shfl_xor_sync(0xffffffffu, s, 1);
        s += __shfl_xor_sync(0xffffffffu, s, 2);
        s += __shfl_xor_sync(0xffffffffu, s, 4);
        s += __shfl_xor_sync(0xffffffffu, s, 8);
        lp[i] = 1.0f / s;
    }

    // ---- epilogue: O/l, scatter into (M, C) layout ----
    const int b = bh >> 4;
    const int h = bh & 15;
#pragma unroll
    for (int i = 0; i < 8; i++) {
        const int t = (qb << 7) + ty * 8 + i;
        float o0, o1, o2, o3;
        UNPACK2(o0, o1, O2[i][0]);
        UNPACK2(o2, o3, O2[i][1]);
        float4 o4 = make_float4(o0 * lp[i], o1 * lp[i], o2 * lp[i], o3 * lp[i]);
        *(float4*)(gy + (size_t)(b * TT + t) * CC + h * DD + tx * 4) = o4;
    }
}

// =================================================================
// launch
// =================================================================
extern "C" void kernel_launch(void* const* d_in, const int* in_sizes, int n_in,
                              void* d_out, int out_size)
{
    const float* x        = (const float*)d_in[0];
    const float* ve       = (const float*)d_in[1];
    const float* qkv_w    = (const float*)d_in[2];
    const float* lambdas  = (const float*)d_in[3];
    const float* c_proj_w = (const float*)d_in[4];
    float* out = (float*)d_out;

    float *qkv_p, *q_p, *k_p, *v_p, *y_p;
    cudaGetSymbolAddress((void**)&qkv_p, g_qkv);
    cudaGetSymbolAddress((void**)&q_p, g_q);
    cudaGetSymbolAddress((void**)&k_p, g_k);
    cudaGetSymbolAddress((void**)&v_p, g_v);
    cudaGetSymbolAddress((void**)&y_p, g_y);

    const int flash_smem = (8192 + 4096 + 64 * VS_STRIDE + 8192) * 4;  // 99328 B
    cudaFuncSetAttribute(flash_attn, cudaFuncAttributeMaxDynamicSharedMemorySize, flash_smem);

    // 1) qkv = x @ qkv_w^T
    sgemm_nt<<<dim3(N_QKV / 128, MM / 128), 256>>>(x, qkv_w, qkv_p, MM, N_QKV, CC);

    // 2) v-mix + rmsnorm + rotary, reshuffle into (B*H, T, D)
    postproc<<<(MM * HH) / 8, 256>>>(qkv_p, ve, lambdas, q_p, k_p, v_p);

    // 3) causal flash attention -> (M, C)
    flash_attn<<<dim3(TT / 128, BB * HH), 256, flash_smem>>>(q_p, k_p, v_p, y_p);

    // 4) out = y @ c_proj_w^T
    sgemm_nt<<<dim3(CC / 128, MM / 128), 256>>>(y_p, c_proj_w, out, MM, CC, CC);
}

// round 6
// speedup vs baseline: 1.5805x; 1.4699x over previous
#include <cuda_runtime.h>
#include <cuda_bf16.h>
#include <math.h>
#include <stdint.h>

// Problem constants
#define BB 4
#define TT 2048
#define CC 1024
#define HH 16
#define DD 64
#define MM (BB * TT)         // 8192
#define N_QKV (3 * CC)       // 3072
#define ATTN_SCALE 0.12f
#define RMS_EPS 1e-6f

typedef unsigned long long ull;

#define FMA2(d, a, b, c) \
    asm("fma.rn.f32x2 %0, %1, %2, %3;" : "=l"(d) : "l"(a), "l"(b), "l"(c))
#define PACK2(d, x) \
    asm("mov.b64 %0, {%1, %1};" : "=l"(d) : "f"(x))
#define UNPACK2(lo, hi, v) \
    asm("mov.b64 {%0, %1}, %2;" : "=f"(lo), "=f"(hi) : "l"(v))

// ---------------- device scratch (allocation-free) ----------------
__device__ float g_qkv[(size_t)MM * N_QKV];          // (M, 3C)
__device__ float g_q[(size_t)BB * HH * TT * DD];     // (B*H, T, D)
__device__ float g_k[(size_t)BB * HH * TT * DD];
__device__ float g_v[(size_t)BB * HH * TT * DD];
__device__ float g_y[(size_t)MM * CC];               // (M, C)

// =================================================================
// mma.sync bf16x3 GEMM:  C = A * B^T
// A (M,K) row-major fp32, B (N,K) row-major fp32, C (M,N) fp32.
// CTA tile 128x128, BK=32, 256 threads (8 warps, warp tile 64x32).
// fp32 split hi/lo bf16; 3 MMAs per tile-kstep: hh + hl + lh.
// Smem rows stride 40 bf16 (20 words) -> conflict-free frag loads.
// =================================================================
#define SROW 20    // words (uint32 = 2 bf16) per smem row

__device__ __forceinline__ void mma16816(float* d, const uint32_t* a, const uint32_t* b) {
    asm volatile(
        "mma.sync.aligned.m16n8k16.row.col.f32.bf16.bf16.f32 "
        "{%0,%1,%2,%3}, {%4,%5,%6,%7}, {%8,%9}, {%0,%1,%2,%3};"
        : "+f"(d[0]), "+f"(d[1]), "+f"(d[2]), "+f"(d[3])
        : "r"(a[0]), "r"(a[1]), "r"(a[2]), "r"(a[3]), "r"(b[0]), "r"(b[1]));
}

// convert 8 consecutive fp32 -> 4 packed bf16x2 hi words + 4 lo words
__device__ __forceinline__ void cvt8(const float* __restrict__ src,
                                     uint32_t* h, uint32_t* l) {
    float4 f0 = *(const float4*)src;
    float4 f1 = *(const float4*)(src + 4);
    float f[8] = {f0.x, f0.y, f0.z, f0.w, f1.x, f1.y, f1.z, f1.w};
#pragma unroll
    for (int j = 0; j < 4; j++) {
        __nv_bfloat16 h0 = __float2bfloat16(f[2 * j]);
        __nv_bfloat16 h1 = __float2bfloat16(f[2 * j + 1]);
        __nv_bfloat16 l0 = __float2bfloat16(f[2 * j]     - __bfloat162float(h0));
        __nv_bfloat16 l1 = __float2bfloat16(f[2 * j + 1] - __bfloat162float(h1));
        h[j] = (uint32_t)__bfloat16_as_ushort(h0) |
               ((uint32_t)__bfloat16_as_ushort(h1) << 16);
        l[j] = (uint32_t)__bfloat16_as_ushort(l0) |
               ((uint32_t)__bfloat16_as_ushort(l1) << 16);
    }
}

__global__ __launch_bounds__(256, 2)
void mma_gemm_bf16x3(const float* __restrict__ A, const float* __restrict__ B,
                     float* __restrict__ C, int M, int N, int K)
{
    __shared__ uint32_t Ah[128 * SROW];
    __shared__ uint32_t Al[128 * SROW];
    __shared__ uint32_t Bh[128 * SROW];
    __shared__ uint32_t Bl[128 * SROW];

    const int tid = threadIdx.x;
    const int wid = tid >> 5;
    const int lane = tid & 31;
    const int g = lane >> 2;         // 0..7
    const int tig = lane & 3;        // 0..3
    const int wm = (wid & 1) * 64;   // warp m offset
    const int wn = (wid >> 1) * 32;  // warp n offset

    const int bm = blockIdx.y * 128;
    const int bn = blockIdx.x * 128;

    // loader: thread -> (row = tid/2, half = tid&1): 16 fp32 of A and of B
    const int lrow = tid >> 1;
    const int lhalf = tid & 1;
    const float* Asrc = A + (size_t)(bm + lrow) * K + lhalf * 16;
    const float* Bsrc = B + (size_t)(bn + lrow) * K + lhalf * 16;
    const int ldst = lrow * SROW + lhalf * 8;   // word offset

    float acc[4][4][4];
#pragma unroll
    for (int mt = 0; mt < 4; mt++)
#pragma unroll
        for (int nt = 0; nt < 4; nt++)
#pragma unroll
            for (int r = 0; r < 4; r++) acc[mt][nt][r] = 0.0f;

    for (int kc = 0; kc < K; kc += 32) {
        __syncthreads();
        // ---- load + split-convert this K-chunk ----
        {
            uint32_t h[4], l[4];
            cvt8(Asrc + kc, h, l);
            *(uint4*)(Ah + ldst) = make_uint4(h[0], h[1], h[2], h[3]);
            *(uint4*)(Al + ldst) = make_uint4(l[0], l[1], l[2], l[3]);
            cvt8(Asrc + kc + 8, h, l);
            *(uint4*)(Ah + ldst + 4) = make_uint4(h[0], h[1], h[2], h[3]);
            *(uint4*)(Al + ldst + 4) = make_uint4(l[0], l[1], l[2], l[3]);
            cvt8(Bsrc + kc, h, l);
            *(uint4*)(Bh + ldst) = make_uint4(h[0], h[1], h[2], h[3]);
            *(uint4*)(Bl + ldst) = make_uint4(l[0], l[1], l[2], l[3]);
            cvt8(Bsrc + kc + 8, h, l);
            *(uint4*)(Bh + ldst + 4) = make_uint4(h[0], h[1], h[2], h[3]);
            *(uint4*)(Bl + ldst + 4) = make_uint4(l[0], l[1], l[2], l[3]);
        }
        __syncthreads();

        // ---- compute: 2 ksteps of 16 ----
#pragma unroll
        for (int ks = 0; ks < 2; ks++) {
            const int kw = ks * 8;
            uint32_t bh[4][2], bl[4][2];
#pragma unroll
            for (int nt = 0; nt < 4; nt++) {
                const int nb = (wn + nt * 8 + g) * SROW + kw + tig;
                bh[nt][0] = Bh[nb]; bh[nt][1] = Bh[nb + 4];
                bl[nt][0] = Bl[nb]; bl[nt][1] = Bl[nb + 4];
            }
#pragma unroll
            for (int mt = 0; mt < 4; mt++) {
                const int ab = (wm + mt * 16 + g) * SROW + kw + tig;
                uint32_t ah[4], al[4];
                ah[0] = Ah[ab];
                ah[1] = Ah[ab + 8 * SROW];
                ah[2] = Ah[ab + 4];
                ah[3] = Ah[ab + 8 * SROW + 4];
                al[0] = Al[ab];
                al[1] = Al[ab + 8 * SROW];
                al[2] = Al[ab + 4];
                al[3] = Al[ab + 8 * SROW + 4];
#pragma unroll
                for (int nt = 0; nt < 4; nt++) {
                    mma16816(acc[mt][nt], ah, bh[nt]);
                    mma16816(acc[mt][nt], ah, bl[nt]);
                    mma16816(acc[mt][nt], al, bh[nt]);
                }
            }
        }
    }

    // ---- epilogue ----
#pragma unroll
    for (int mt = 0; mt < 4; mt++) {
        const int r0 = bm + wm + mt * 16 + g;
#pragma unroll
        for (int nt = 0; nt < 4; nt++) {
            const int col = bn + wn + nt * 8 + tig * 2;
            *(float2*)&C[(size_t)r0 * N + col] =
                make_float2(acc[mt][nt][0], acc[mt][nt][1]);
            *(float2*)&C[(size_t)(r0 + 8) * N + col] =
                make_float2(acc[mt][nt][2], acc[mt][nt][3]);
        }
    }
}

// =================================================================
// Post-process: v = l0*v + l1*ve ; rmsnorm(q), rmsnorm(k) ; rotary.
// =================================================================
__global__ __launch_bounds__(256)
void postproc(const float* __restrict__ qkv, const float* __restrict__ ve,
              const float* __restrict__ lambdas,
              float* __restrict__ gq, float* __restrict__ gk, float* __restrict__ gv)
{
    const int pair = blockIdx.x * 8 + (threadIdx.x >> 5);
    const int l = threadIdx.x & 31;
    const int m = pair >> 4;
    const int h = pair & 15;
    const int t = m & (TT - 1);
    const int b = m >> 11;

    const float* row = qkv + (size_t)m * N_QKV + h * DD;
    float q0 = row[l],          q1 = row[l + 32];
    float k0 = row[CC + l],     k1 = row[CC + l + 32];
    float v0 = row[2 * CC + l], v1 = row[2 * CC + l + 32];

    const float lam0 = lambdas[0], lam1 = lambdas[1];
    const float* verow = ve + (size_t)m * CC + h * DD;
    v0 = lam0 * v0 + lam1 * verow[l];
    v1 = lam0 * v1 + lam1 * verow[l + 32];

    float sq = q0 * q0 + q1 * q1;
    float sk = k0 * k0 + k1 * k1;
#pragma unroll
    for (int o = 16; o; o >>= 1) {
        sq += __shfl_xor_sync(0xffffffffu, sq, o);
        sk += __shfl_xor_sync(0xffffffffu, sk, o);
    }
    float rq = 1.0f / sqrtf(sq * (1.0f / 64.0f) + RMS_EPS);
    float rk = 1.0f / sqrtf(sk * (1.0f / 64.0f) + RMS_EPS);
    q0 *= rq; q1 *= rq;
    k0 *= rk; k1 *= rk;

    float ang = (l < 16) ? (float)exp2(-(10.0 / 15.0) * (double)l) : 0.0f;
    float th = (float)t * ang;
    float s, c;
    sincosf(th, &s, &c);
    float qa = q0 * c + q1 * s;
    float qb = q1 * c - q0 * s;
    float ka = k0 * c + k1 * s;
    float kb = k1 * c - k0 * s;

    size_t o = ((size_t)(b * HH + h) * TT + t) * DD + l;
    gq[o] = qa; gq[o + 32] = qb;
    gk[o] = ka; gk[o + 32] = kb;
    gv[o] = v0; gv[o + 32] = v1;
}

// =================================================================
// Flash attention (causal), no-max softmax (|s| <= 7.68 since
// rms_norm gives ||q||=||k||=8, scale 0.12 => exp safe in fp32).
// (unchanged from the passing R4 version)
// =================================================================
#define VS_STRIDE 68

__global__ __launch_bounds__(256, 2)
void flash_attn(const float* __restrict__ gq, const float* __restrict__ gk,
                const float* __restrict__ gv, float* __restrict__ gy)
{
    extern __shared__ float sm[];
    float* QsT = sm;
    float* KsT = sm + 8192;
    float* Vs  = sm + 8192 + 4096;
    float* Ps  = sm + 8192 + 4096 + 4352;

    const int bh = blockIdx.y;
    const int qb = (int)gridDim.x - 1 - (int)blockIdx.x;
    const int tid = threadIdx.x;
    const int tx = tid & 15;
    const int ty = tid >> 4;

    const size_t base = (size_t)bh * TT * DD;
    const float* Q = gq + base;
    const float* K = gk + base;
    const float* V = gv + base;

    {
        const int r = tid & 127;
        const int d0 = (tid >> 7) << 5;
        const float* qrow = Q + ((size_t)((qb << 7) + r) << 6) + d0;
#pragma unroll
        for (int u = 0; u < 8; u++) {
            float4 t4 = *(const float4*)(qrow + 4 * u);
            QsT[(d0 + 4 * u + 0) * 128 + r] = t4.x;
            QsT[(d0 + 4 * u + 1) * 128 + r] = t4.y;
            QsT[(d0 + 4 * u + 2) * 128 + r] = t4.z;
            QsT[(d0 + 4 * u + 3) * 128 + r] = t4.w;
        }
    }

    ull O2[8][2];
    float lp[8];
#pragma unroll
    for (int i = 0; i < 8; i++) {
        lp[i] = 0.0f;
        O2[i][0] = 0ull; O2[i][1] = 0ull;
    }

    const int kvr = tid & 63;
    const int kvd0 = (tid >> 6) << 4;

    const int nkb = 2 * qb + 2;
    for (int kb = 0; kb < nkb; kb++) {
        __syncthreads();
        {
            const float* krow = K + ((size_t)((kb << 6) + kvr) << 6) + kvd0;
            const float* vrow = V + ((size_t)((kb << 6) + kvr) << 6) + kvd0;
#pragma unroll
            for (int u = 0; u < 4; u++) {
                float4 t4 = *(const float4*)(krow + 4 * u);
                KsT[(kvd0 + 4 * u + 0) * 64 + kvr] = t4.x;
                KsT[(kvd0 + 4 * u + 1) * 64 + kvr] = t4.y;
                KsT[(kvd0 + 4 * u + 2) * 64 + kvr] = t4.z;
                KsT[(kvd0 + 4 * u + 3) * 64 + kvr] = t4.w;
                *(float4*)(Vs + kvr * VS_STRIDE + kvd0 + 4 * u) =
                    *(const float4*)(vrow + 4 * u);
            }
        }
        __syncthreads();

        ull sacc[8][2];
#pragma unroll
        for (int i = 0; i < 8; i++) { sacc[i][0] = 0ull; sacc[i][1] = 0ull; }

#pragma unroll 2
        for (int d = 0; d < 64; d++) {
            float a[8];
            *(float4*)&a[0] = *(const float4*)(QsT + d * 128 + ty * 8);
            *(float4*)&a[4] = *(const float4*)(QsT + d * 128 + ty * 8 + 4);
            ull b2[2];
            b2[0] = *(const ull*)(KsT + d * 64 + tx * 4);
            b2[1] = *(const ull*)(KsT + d * 64 + tx * 4 + 2);
            ull aa[8];
#pragma unroll
            for (int i = 0; i < 8; i++) PACK2(aa[i], a[i]);
#pragma unroll
            for (int i = 0; i < 8; i++) {
                FMA2(sacc[i][0], aa[i], b2[0], sacc[i][0]);
                FMA2(sacc[i][1], aa[i], b2[1], sacc[i][1]);
            }
        }

        const bool diag = (kb >= 2 * qb);
        const int grow0 = (qb << 7) + ty * 8;
#pragma unroll
        for (int jj = 0; jj < 2; jj++) {
            float pc[8][2];
#pragma unroll
            for (int i = 0; i < 8; i++) {
                float s0, s1;
                UNPACK2(s0, s1, sacc[i][jj]);
                const int col = (kb << 6) + tx * 4 + jj * 2;
                const int grow = grow0 + i;
                float p0 = (diag && (col > grow)) ? 0.0f : __expf(s0 * ATTN_SCALE);
                float p1 = (diag && (col + 1 > grow)) ? 0.0f : __expf(s1 * ATTN_SCALE);
                pc[i][0] = p0; pc[i][1] = p1;
                lp[i] += p0 + p1;
            }
#pragma unroll
            for (int h2 = 0; h2 < 2; h2++) {
                const int k = tx * 4 + jj * 2 + h2;
                float* dst = Ps + k * 128 + ((ty ^ tx) << 3);
                *(float4*)dst = make_float4(pc[0][h2], pc[1][h2], pc[2][h2], pc[3][h2]);
                *(float4*)(dst + 4) = make_float4(pc[4][h2], pc[5][h2], pc[6][h2], pc[7][h2]);
            }
        }
        __syncthreads();

#pragma unroll 2
        for (int k = 0; k < 64; k++) {
            float p[8];
            const float* pp = Ps + k * 128 + ((ty ^ (k >> 2)) << 3);
            *(float4*)&p[0] = *(const float4*)pp;
            *(float4*)&p[4] = *(const float4*)(pp + 4);
            ull v2[2];
            v2[0] = *(const ull*)(Vs + k * VS_STRIDE + tx * 4);
            v2[1] = *(const ull*)(Vs + k * VS_STRIDE + tx * 4 + 2);
            ull pk[8];
#pragma unroll
            for (int i = 0; i < 8; i++) PACK2(pk[i], p[i]);
#pragma unroll
            for (int i = 0; i < 8; i++) {
                FMA2(O2[i][0], pk[i], v2[0], O2[i][0]);
                FMA2(O2[i][1], pk[i], v2[1], O2[i][1]);
            }
        }
    }

#pragma unroll
    for (int i = 0; i < 8; i++) {
        float s = lp[i];
        s += __shfl_xor_sync(0xffffffffu, s, 1);
        s += __shfl_xor_sync(0xffffffffu, s, 2);
        s += __shfl_xor_sync(0xffffffffu, s, 4);
        s += __shfl_xor_sync(0xffffffffu, s, 8);
        lp[i] = 1.0f / s;
    }

    const int b = bh >> 4;
    const int h = bh & 15;
#pragma unroll
    for (int i = 0; i < 8; i++) {
        const int t = (qb << 7) + ty * 8 + i;
        float o0, o1, o2, o3;
        UNPACK2(o0, o1, O2[i][0]);
        UNPACK2(o2, o3, O2[i][1]);
        float4 o4 = make_float4(o0 * lp[i], o1 * lp[i], o2 * lp[i], o3 * lp[i]);
        *(float4*)(gy + (size_t)(b * TT + t) * CC + h * DD + tx * 4) = o4;
    }
}

// =================================================================
// launch
// =================================================================
extern "C" void kernel_launch(void* const* d_in, const int* in_sizes, int n_in,
                              void* d_out, int out_size)
{
    const float* x        = (const float*)d_in[0];
    const float* ve       = (const float*)d_in[1];
    const float* qkv_w    = (const float*)d_in[2];
    const float* lambdas  = (const float*)d_in[3];
    const float* c_proj_w = (const float*)d_in[4];
    float* out = (float*)d_out;

    float *qkv_p, *q_p, *k_p, *v_p, *y_p;
    cudaGetSymbolAddress((void**)&qkv_p, g_qkv);
    cudaGetSymbolAddress((void**)&q_p, g_q);
    cudaGetSymbolAddress((void**)&k_p, g_k);
    cudaGetSymbolAddress((void**)&v_p, g_v);
    cudaGetSymbolAddress((void**)&y_p, g_y);

    const int flash_smem = (8192 + 4096 + 64 * VS_STRIDE + 8192) * 4;  // 99328 B
    cudaFuncSetAttribute(flash_attn, cudaFuncAttributeMaxDynamicSharedMemorySize, flash_smem);

    // 1) qkv = x @ qkv_w^T  (mma.sync bf16x3)
    mma_gemm_bf16x3<<<dim3(N_QKV / 128, MM / 128), 256>>>(x, qkv_w, qkv_p, MM, N_QKV, CC);

    // 2) v-mix + rmsnorm + rotary
    postproc<<<(MM * HH) / 8, 256>>>(qkv_p, ve, lambdas, q_p, k_p, v_p);

    // 3) causal flash attention -> (M, C)
    flash_attn<<<dim3(TT / 128, BB * HH), 256, flash_smem>>>(q_p, k_p, v_p, y_p);

    // 4) out = y @ c_proj_w^T  (mma.sync bf16x3)
    mma_gemm_bf16x3<<<dim3(CC / 128, MM / 128), 256>>>(y_p, c_proj_w, out, MM, CC, CC);
}

// round 7
// speedup vs baseline: 1.5845x; 1.0025x over previous
#include <cuda_runtime.h>
#include <cuda_bf16.h>
#include <math.h>
#include <stdint.h>

// Problem constants
#define BB 4
#define TT 2048
#define CC 1024
#define HH 16
#define DD 64
#define MM (BB * TT)         // 8192
#define N_QKV (3 * CC)       // 3072
#define ATTN_SCALE 0.12f
#define RMS_EPS 1e-6f

typedef unsigned long long ull;

#define FMA2(d, a, b, c) \
    asm("fma.rn.f32x2 %0, %1, %2, %3;" : "=l"(d) : "l"(a), "l"(b), "l"(c))
#define PACK2(d, x) \
    asm("mov.b64 %0, {%1, %1};" : "=l"(d) : "f"(x))
#define UNPACK2(lo, hi, v) \
    asm("mov.b64 {%0, %1}, %2;" : "=f"(lo), "=f"(hi) : "l"(v))

// ---------------- device scratch (allocation-free) ----------------
__device__ float g_qkv[(size_t)MM * N_QKV];          // (M, 3C)
__device__ float g_q[(size_t)BB * HH * TT * DD];     // (B*H, T, D)
__device__ float g_k[(size_t)BB * HH * TT * DD];
__device__ float g_v[(size_t)BB * HH * TT * DD];
__device__ float g_y[(size_t)MM * CC];               // (M, C)
// bf16 hi/lo split buffers
__device__ __nv_bfloat16 g_xh[(size_t)MM * CC],     g_xl[(size_t)MM * CC];
__device__ __nv_bfloat16 g_wh[(size_t)N_QKV * CC],  g_wl[(size_t)N_QKV * CC];
__device__ __nv_bfloat16 g_yh[(size_t)MM * CC],     g_yl[(size_t)MM * CC];
__device__ __nv_bfloat16 g_ph[(size_t)CC * CC],     g_pl[(size_t)CC * CC];

// =================================================================
// split: fp32 -> bf16 hi + bf16 lo (residual)
// =================================================================
__global__ __launch_bounds__(256)
void split_bf16(const float* __restrict__ in,
                __nv_bfloat16* __restrict__ hi, __nv_bfloat16* __restrict__ lo,
                int n)
{
    const int i = (blockIdx.x * 256 + threadIdx.x) * 4;
    if (i >= n) return;
    float4 f4 = *(const float4*)(in + i);
    float f[4] = {f4.x, f4.y, f4.z, f4.w};
    uint16_t h[4], l[4];
#pragma unroll
    for (int j = 0; j < 4; j++) {
        __nv_bfloat16 hb = __float2bfloat16(f[j]);
        __nv_bfloat16 lb = __float2bfloat16(f[j] - __bfloat162float(hb));
        h[j] = __bfloat16_as_ushort(hb);
        l[j] = __bfloat16_as_ushort(lb);
    }
    uint2 hp = make_uint2((uint32_t)h[0] | ((uint32_t)h[1] << 16),
                          (uint32_t)h[2] | ((uint32_t)h[3] << 16));
    uint2 lp = make_uint2((uint32_t)l[0] | ((uint32_t)l[1] << 16),
                          (uint32_t)l[2] | ((uint32_t)l[3] << 16));
    *(uint2*)(hi + i) = hp;
    *(uint2*)(lo + i) = lp;
}

// =================================================================
// mma.sync bf16x3 GEMM with pre-split inputs + cp.async double buffer
// C = A * B^T, A (M,K) bf16 hi/lo, B (N,K) bf16 hi/lo, C (M,N) fp32.
// CTA tile 128x128, BK=32, 256 threads (8 warps, warp tile 64x32).
// Smem: 2 buffers x 4 arrays x 128 rows x 20 words (16 data + 4 pad).
// =================================================================
#define SROW 20                   // words per smem row
#define ARR_W (128 * SROW)        // 2560 words per array
#define BUF_W (4 * ARR_W)         // 10240 words per buffer
#define GEMM_SMEM (2 * BUF_W * 4) // 81920 bytes

__device__ __forceinline__ uint32_t smem_u32(const void* p) {
    uint32_t a;
    asm("{ .reg .u64 t; cvta.to.shared.u64 t, %1; cvt.u32.u64 %0, t; }"
        : "=r"(a) : "l"(p));
    return a;
}

__device__ __forceinline__ void mma16816(float* d, const uint32_t* a, const uint32_t* b) {
    asm volatile(
        "mma.sync.aligned.m16n8k16.row.col.f32.bf16.bf16.f32 "
        "{%0,%1,%2,%3}, {%4,%5,%6,%7}, {%8,%9}, {%0,%1,%2,%3};"
        : "+f"(d[0]), "+f"(d[1]), "+f"(d[2]), "+f"(d[3])
        : "r"(a[0]), "r"(a[1]), "r"(a[2]), "r"(a[3]), "r"(b[0]), "r"(b[1]));
}

#define CP_ASYNC(dst, src) \
    asm volatile("cp.async.cg.shared.global [%0], [%1], 16;" \
                 :: "r"(dst), "l"(src) : "memory")
#define CP_COMMIT() asm volatile("cp.async.commit_group;" ::: "memory")
#define CP_WAIT1()  asm volatile("cp.async.wait_group 1;" ::: "memory")

__global__ __launch_bounds__(256, 2)
void mma_gemm_pre(const __nv_bfloat16* __restrict__ Ahg,
                  const __nv_bfloat16* __restrict__ Alg,
                  const __nv_bfloat16* __restrict__ Bhg,
                  const __nv_bfloat16* __restrict__ Blg,
                  float* __restrict__ C, int M, int N, int K)
{
    extern __shared__ uint32_t sw[];
    const uint32_t sbase = smem_u32(sw);

    const int tid = threadIdx.x;
    const int wid = tid >> 5;
    const int lane = tid & 31;
    const int g = lane >> 2;
    const int tig = lane & 3;
    const int wm = (wid & 1) * 64;
    const int wn = (wid >> 1) * 32;

    const int bm = blockIdx.y * 128;
    const int bn = blockIdx.x * 128;

    // loader mapping: thread -> 2 segments; seg s: row = s>>2, seg16 = s&3
    const int s0 = tid * 2;
    const int lrow0 = s0 >> 2, lseg0 = s0 & 3;
    const int lrow1 = (s0 + 1) >> 2, lseg1 = (s0 + 1) & 3;

    float acc[4][4][4];
#pragma unroll
    for (int mt = 0; mt < 4; mt++)
#pragma unroll
        for (int nt = 0; nt < 4; nt++)
#pragma unroll
            for (int r = 0; r < 4; r++) acc[mt][nt][r] = 0.0f;

    const int nch = K >> 5;

    // chunk issue: 8 cp.asyncs per thread
    auto issue = [&](int ci, int buf) {
        const int kc = ci << 5;
        const uint32_t bb = sbase + buf * (BUF_W * 4);
#pragma unroll
        for (int j = 0; j < 2; j++) {
            const int row = j ? lrow1 : lrow0;
            const int seg = j ? lseg1 : lseg0;
            const size_t goff = (size_t)(bm + row) * K + kc + seg * 8;
            const size_t goffB = (size_t)(bn + row) * K + kc + seg * 8;
            const uint32_t soff = (row * SROW + seg * 4) * 4;
            CP_ASYNC(bb + 0 * ARR_W * 4 + soff, Ahg + goff);
            CP_ASYNC(bb + 1 * ARR_W * 4 + soff, Alg + goff);
            CP_ASYNC(bb + 2 * ARR_W * 4 + soff, Bhg + goffB);
            CP_ASYNC(bb + 3 * ARR_W * 4 + soff, Blg + goffB);
        }
    };

    issue(0, 0); CP_COMMIT();
    issue(1, 1); CP_COMMIT();

    for (int ci = 0; ci < nch; ci++) {
        const int buf = ci & 1;
        CP_WAIT1();
        __syncthreads();

        const uint32_t* Ah = sw + buf * BUF_W;
        const uint32_t* Al = Ah + ARR_W;
        const uint32_t* Bh = Ah + 2 * ARR_W;
        const uint32_t* Bl = Ah + 3 * ARR_W;

#pragma unroll
        for (int ks = 0; ks < 2; ks++) {
            const int kw = ks * 8;
            uint32_t bhf[4][2], blf[4][2];
#pragma unroll
            for (int nt = 0; nt < 4; nt++) {
                const int nb = (wn + nt * 8 + g) * SROW + kw + tig;
                bhf[nt][0] = Bh[nb]; bhf[nt][1] = Bh[nb + 4];
                blf[nt][0] = Bl[nb]; blf[nt][1] = Bl[nb + 4];
            }
#pragma unroll
            for (int mt = 0; mt < 4; mt++) {
                const int ab = (wm + mt * 16 + g) * SROW + kw + tig;
                uint32_t ah[4], al[4];
                ah[0] = Ah[ab];
                ah[1] = Ah[ab + 8 * SROW];
                ah[2] = Ah[ab + 4];
                ah[3] = Ah[ab + 8 * SROW + 4];
                al[0] = Al[ab];
                al[1] = Al[ab + 8 * SROW];
                al[2] = Al[ab + 4];
                al[3] = Al[ab + 8 * SROW + 4];
#pragma unroll
                for (int nt = 0; nt < 4; nt++) {
                    mma16816(acc[mt][nt], ah, bhf[nt]);
                    mma16816(acc[mt][nt], ah, blf[nt]);
                    mma16816(acc[mt][nt], al, bhf[nt]);
                }
            }
        }
        __syncthreads();
        if (ci + 2 < nch) issue(ci + 2, buf);
        CP_COMMIT();
    }

    // ---- epilogue ----
#pragma unroll
    for (int mt = 0; mt < 4; mt++) {
        const int r0 = bm + wm + mt * 16 + g;
#pragma unroll
        for (int nt = 0; nt < 4; nt++) {
            const int col = bn + wn + nt * 8 + tig * 2;
            *(float2*)&C[(size_t)r0 * N + col] =
                make_float2(acc[mt][nt][0], acc[mt][nt][1]);
            *(float2*)&C[(size_t)(r0 + 8) * N + col] =
                make_float2(acc[mt][nt][2], acc[mt][nt][3]);
        }
    }
}

// =================================================================
// Post-process: v = l0*v + l1*ve ; rmsnorm(q), rmsnorm(k) ; rotary.
// =================================================================
__global__ __launch_bounds__(256)
void postproc(const float* __restrict__ qkv, const float* __restrict__ ve,
              const float* __restrict__ lambdas,
              float* __restrict__ gq, float* __restrict__ gk, float* __restrict__ gv)
{
    const int pair = blockIdx.x * 8 + (threadIdx.x >> 5);
    const int l = threadIdx.x & 31;
    const int m = pair >> 4;
    const int h = pair & 15;
    const int t = m & (TT - 1);
    const int b = m >> 11;

    const float* row = qkv + (size_t)m * N_QKV + h * DD;
    float q0 = row[l],          q1 = row[l + 32];
    float k0 = row[CC + l],     k1 = row[CC + l + 32];
    float v0 = row[2 * CC + l], v1 = row[2 * CC + l + 32];

    const float lam0 = lambdas[0], lam1 = lambdas[1];
    const float* verow = ve + (size_t)m * CC + h * DD;
    v0 = lam0 * v0 + lam1 * verow[l];
    v1 = lam0 * v1 + lam1 * verow[l + 32];

    float sq = q0 * q0 + q1 * q1;
    float sk = k0 * k0 + k1 * k1;
#pragma unroll
    for (int o = 16; o; o >>= 1) {
        sq += __shfl_xor_sync(0xffffffffu, sq, o);
        sk += __shfl_xor_sync(0xffffffffu, sk, o);
    }
    float rq = 1.0f / sqrtf(sq * (1.0f / 64.0f) + RMS_EPS);
    float rk = 1.0f / sqrtf(sk * (1.0f / 64.0f) + RMS_EPS);
    q0 *= rq; q1 *= rq;
    k0 *= rk; k1 *= rk;

    float ang = (l < 16) ? (float)exp2(-(10.0 / 15.0) * (double)l) : 0.0f;
    float th = (float)t * ang;
    float s, c;
    sincosf(th, &s, &c);
    float qa = q0 * c + q1 * s;
    float qb = q1 * c - q0 * s;
    float ka = k0 * c + k1 * s;
    float kb = k1 * c - k0 * s;

    size_t o = ((size_t)(b * HH + h) * TT + t) * DD + l;
    gq[o] = qa; gq[o + 32] = qb;
    gk[o] = ka; gk[o + 32] = kb;
    gv[o] = v0; gv[o + 32] = v1;
}

// =================================================================
// Flash attention (causal), no-max softmax. (unchanged, passing)
// =================================================================
#define VS_STRIDE 68

__global__ __launch_bounds__(256, 2)
void flash_attn(const float* __restrict__ gq, const float* __restrict__ gk,
                const float* __restrict__ gv, float* __restrict__ gy)
{
    extern __shared__ float sm[];
    float* QsT = sm;
    float* KsT = sm + 8192;
    float* Vs  = sm + 8192 + 4096;
    float* Ps  = sm + 8192 + 4096 + 4352;

    const int bh = blockIdx.y;
    const int qb = (int)gridDim.x - 1 - (int)blockIdx.x;
    const int tid = threadIdx.x;
    const int tx = tid & 15;
    const int ty = tid >> 4;

    const size_t base = (size_t)bh * TT * DD;
    const float* Q = gq + base;
    const float* K = gk + base;
    const float* V = gv + base;

    {
        const int r = tid & 127;
        const int d0 = (tid >> 7) << 5;
        const float* qrow = Q + ((size_t)((qb << 7) + r) << 6) + d0;
#pragma unroll
        for (int u = 0; u < 8; u++) {
            float4 t4 = *(const float4*)(qrow + 4 * u);
            QsT[(d0 + 4 * u + 0) * 128 + r] = t4.x;
            QsT[(d0 + 4 * u + 1) * 128 + r] = t4.y;
            QsT[(d0 + 4 * u + 2) * 128 + r] = t4.z;
            QsT[(d0 + 4 * u + 3) * 128 + r] = t4.w;
        }
    }

    ull O2[8][2];
    float lp[8];
#pragma unroll
    for (int i = 0; i < 8; i++) {
        lp[i] = 0.0f;
        O2[i][0] = 0ull; O2[i][1] = 0ull;
    }

    const int kvr = tid & 63;
    const int kvd0 = (tid >> 6) << 4;

    const int nkb = 2 * qb + 2;
    for (int kb = 0; kb < nkb; kb++) {
        __syncthreads();
        {
            const float* krow = K + ((size_t)((kb << 6) + kvr) << 6) + kvd0;
            const float* vrow = V + ((size_t)((kb << 6) + kvr) << 6) + kvd0;
#pragma unroll
            for (int u = 0; u < 4; u++) {
                float4 t4 = *(const float4*)(krow + 4 * u);
                KsT[(kvd0 + 4 * u + 0) * 64 + kvr] = t4.x;
                KsT[(kvd0 + 4 * u + 1) * 64 + kvr] = t4.y;
                KsT[(kvd0 + 4 * u + 2) * 64 + kvr] = t4.z;
                KsT[(kvd0 + 4 * u + 3) * 64 + kvr] = t4.w;
                *(float4*)(Vs + kvr * VS_STRIDE + kvd0 + 4 * u) =
                    *(const float4*)(vrow + 4 * u);
            }
        }
        __syncthreads();

        ull sacc[8][2];
#pragma unroll
        for (int i = 0; i < 8; i++) { sacc[i][0] = 0ull; sacc[i][1] = 0ull; }

#pragma unroll 2
        for (int d = 0; d < 64; d++) {
            float a[8];
            *(float4*)&a[0] = *(const float4*)(QsT + d * 128 + ty * 8);
            *(float4*)&a[4] = *(const float4*)(QsT + d * 128 + ty * 8 + 4);
            ull b2[2];
            b2[0] = *(const ull*)(KsT + d * 64 + tx * 4);
            b2[1] = *(const ull*)(KsT + d * 64 + tx * 4 + 2);
            ull aa[8];
#pragma unroll
            for (int i = 0; i < 8; i++) PACK2(aa[i], a[i]);
#pragma unroll
            for (int i = 0; i < 8; i++) {
                FMA2(sacc[i][0], aa[i], b2[0], sacc[i][0]);
                FMA2(sacc[i][1], aa[i], b2[1], sacc[i][1]);
            }
        }

        const bool diag = (kb >= 2 * qb);
        const int grow0 = (qb << 7) + ty * 8;
#pragma unroll
        for (int jj = 0; jj < 2; jj++) {
            float pc[8][2];
#pragma unroll
            for (int i = 0; i < 8; i++) {
                float s0, s1;
                UNPACK2(s0, s1, sacc[i][jj]);
                const int col = (kb << 6) + tx * 4 + jj * 2;
                const int grow = grow0 + i;
                float p0 = (diag && (col > grow)) ? 0.0f : __expf(s0 * ATTN_SCALE);
                float p1 = (diag && (col + 1 > grow)) ? 0.0f : __expf(s1 * ATTN_SCALE);
                pc[i][0] = p0; pc[i][1] = p1;
                lp[i] += p0 + p1;
            }
#pragma unroll
            for (int h2 = 0; h2 < 2; h2++) {
                const int k = tx * 4 + jj * 2 + h2;
                float* dst = Ps + k * 128 + ((ty ^ tx) << 3);
                *(float4*)dst = make_float4(pc[0][h2], pc[1][h2], pc[2][h2], pc[3][h2]);
                *(float4*)(dst + 4) = make_float4(pc[4][h2], pc[5][h2], pc[6][h2], pc[7][h2]);
            }
        }
        __syncthreads();

#pragma unroll 2
        for (int k = 0; k < 64; k++) {
            float p[8];
            const float* pp = Ps + k * 128 + ((ty ^ (k >> 2)) << 3);
            *(float4*)&p[0] = *(const float4*)pp;
            *(float4*)&p[4] = *(const float4*)(pp + 4);
            ull v2[2];
            v2[0] = *(const ull*)(Vs + k * VS_STRIDE + tx * 4);
            v2[1] = *(const ull*)(Vs + k * VS_STRIDE + tx * 4 + 2);
            ull pk[8];
#pragma unroll
            for (int i = 0; i < 8; i++) PACK2(pk[i], p[i]);
#pragma unroll
            for (int i = 0; i < 8; i++) {
                FMA2(O2[i][0], pk[i], v2[0], O2[i][0]);
                FMA2(O2[i][1], pk[i], v2[1], O2[i][1]);
            }
        }
    }

#pragma unroll
    for (int i = 0; i < 8; i++) {
        float s = lp[i];
        s += __shfl_xor_sync(0xffffffffu, s, 1);
        s += __shfl_xor_sync(0xffffffffu, s, 2);
        s += __shfl_xor_sync(0xffffffffu, s, 4);
        s += __shfl_xor_sync(0xffffffffu, s, 8);
        lp[i] = 1.0f / s;
    }

    const int b = bh >> 4;
    const int h = bh & 15;
#pragma unroll
    for (int i = 0; i < 8; i++) {
        const int t = (qb << 7) + ty * 8 + i;
        float o0, o1, o2, o3;
        UNPACK2(o0, o1, O2[i][0]);
        UNPACK2(o2, o3, O2[i][1]);
        float4 o4 = make_float4(o0 * lp[i], o1 * lp[i], o2 * lp[i], o3 * lp[i]);
        *(float4*)(gy + (size_t)(b * TT + t) * CC + h * DD + tx * 4) = o4;
    }
}

// =================================================================
// launch
// =================================================================
extern "C" void kernel_launch(void* const* d_in, const int* in_sizes, int n_in,
                              void* d_out, int out_size)
{
    const float* x        = (const float*)d_in[0];
    const float* ve       = (const float*)d_in[1];
    const float* qkv_w    = (const float*)d_in[2];
    const float* lambdas  = (const float*)d_in[3];
    const float* c_proj_w = (const float*)d_in[4];
    float* out = (float*)d_out;

    float *qkv_p, *q_p, *k_p, *v_p, *y_p;
    cudaGetSymbolAddress((void**)&qkv_p, g_qkv);
    cudaGetSymbolAddress((void**)&q_p, g_q);
    cudaGetSymbolAddress((void**)&k_p, g_k);
    cudaGetSymbolAddress((void**)&v_p, g_v);
    cudaGetSymbolAddress((void**)&y_p, g_y);
    __nv_bfloat16 *xh, *xl, *wh, *wl, *yh, *yl, *ph, *pl;
    cudaGetSymbolAddress((void**)&xh, g_xh); cudaGetSymbolAddress((void**)&xl, g_xl);
    cudaGetSymbolAddress((void**)&wh, g_wh); cudaGetSymbolAddress((void**)&wl, g_wl);
    cudaGetSymbolAddress((void**)&yh, g_yh); cudaGetSymbolAddress((void**)&yl, g_yl);
    cudaGetSymbolAddress((void**)&ph, g_ph); cudaGetSymbolAddress((void**)&pl, g_pl);

    const int flash_smem = (8192 + 4096 + 64 * VS_STRIDE + 8192) * 4;  // 99328 B
    cudaFuncSetAttribute(flash_attn, cudaFuncAttributeMaxDynamicSharedMemorySize, flash_smem);
    cudaFuncSetAttribute(mma_gemm_pre, cudaFuncAttributeMaxDynamicSharedMemorySize, GEMM_SMEM);

    // 0) pre-split fp32 -> bf16 hi/lo
    split_bf16<<<(MM * CC) / 1024, 256>>>(x, xh, xl, MM * CC);
    split_bf16<<<(N_QKV * CC) / 1024, 256>>>(qkv_w, wh, wl, N_QKV * CC);

    // 1) qkv = x @ qkv_w^T
    mma_gemm_pre<<<dim3(N_QKV / 128, MM / 128), 256, GEMM_SMEM>>>(
        xh, xl, wh, wl, qkv_p, MM, N_QKV, CC);

    // 2) v-mix + rmsnorm + rotary
    postproc<<<(MM * HH) / 8, 256>>>(qkv_p, ve, lambdas, q_p, k_p, v_p);

    // 3) causal flash attention -> (M, C)
    flash_attn<<<dim3(TT / 128, BB * HH), 256, flash_smem>>>(q_p, k_p, v_p, y_p);

    // 4) split y and c_proj_w, then out = y @ c_proj_w^T
    split_bf16<<<(MM * CC) / 1024, 256>>>(y_p, yh, yl, MM * CC);
    split_bf16<<<(CC * CC) / 1024, 256>>>(c_proj_w, ph, pl, CC * CC);
    mma_gemm_pre<<<dim3(CC / 128, MM / 128), 256, GEMM_SMEM>>>(
        yh, yl, ph, pl, out, MM, CC, CC);
}

// round 8
// speedup vs baseline: 2.2606x; 1.4267x over previous
#include <cuda_runtime.h>
#include <cuda_bf16.h>
#include <math.h>
#include <stdint.h>

// Problem constants
#define BB 4
#define TT 2048
#define CC 1024
#define HH 16
#define DD 64
#define MM (BB * TT)         // 8192
#define N_QKV (3 * CC)       // 3072
#define ATTN_SCALE 0.12f
#define RMS_EPS 1e-6f

// ---------------- device scratch (allocation-free) ----------------
__device__ float g_qkv[(size_t)MM * N_QKV];          // (M, 3C)
// bf16 hi/lo split buffers for GEMMs
__device__ __nv_bfloat16 g_xh[(size_t)MM * CC],     g_xl[(size_t)MM * CC];
__device__ __nv_bfloat16 g_wh[(size_t)N_QKV * CC],  g_wl[(size_t)N_QKV * CC];
__device__ __nv_bfloat16 g_yh[(size_t)MM * CC],     g_yl[(size_t)MM * CC];
__device__ __nv_bfloat16 g_ph[(size_t)CC * CC],     g_pl[(size_t)CC * CC];
// attention operands (B*H, T, D) bf16 hi/lo; v also transposed (B*H, D, T)
#define AHD ((size_t)BB * HH * TT * DD)
__device__ __nv_bfloat16 g_qh[AHD], g_ql[AHD];
__device__ __nv_bfloat16 g_kh[AHD], g_kl[AHD];
__device__ __nv_bfloat16 g_vh[AHD], g_vl[AHD];
__device__ __nv_bfloat16 g_vth[AHD], g_vtl[AHD];

// =================================================================
// common helpers
// =================================================================
__device__ __forceinline__ uint32_t smem_u32(const void* p) {
    uint32_t a;
    asm("{ .reg .u64 t; cvta.to.shared.u64 t, %1; cvt.u32.u64 %0, t; }"
        : "=r"(a) : "l"(p));
    return a;
}

__device__ __forceinline__ void mma16816(float* d, const uint32_t* a, const uint32_t* b) {
    asm volatile(
        "mma.sync.aligned.m16n8k16.row.col.f32.bf16.bf16.f32 "
        "{%0,%1,%2,%3}, {%4,%5,%6,%7}, {%8,%9}, {%0,%1,%2,%3};"
        : "+f"(d[0]), "+f"(d[1]), "+f"(d[2]), "+f"(d[3])
        : "r"(a[0]), "r"(a[1]), "r"(a[2]), "r"(a[3]), "r"(b[0]), "r"(b[1]));
}

#define CP_ASYNC(dst, src) \
    asm volatile("cp.async.cg.shared.global [%0], [%1], 16;" \
                 :: "r"(dst), "l"(src) : "memory")
#define CP_COMMIT() asm volatile("cp.async.commit_group;" ::: "memory")
#define CP_WAIT1()  asm volatile("cp.async.wait_group 1;" ::: "memory")

__device__ __forceinline__ uint32_t pack_bf16(float a, float b) {
    __nv_bfloat16 ha = __float2bfloat16(a);
    __nv_bfloat16 hb = __float2bfloat16(b);
    return (uint32_t)__bfloat16_as_ushort(ha) |
           ((uint32_t)__bfloat16_as_ushort(hb) << 16);
}

// =================================================================
// split: fp32 -> bf16 hi + bf16 lo (residual)
// =================================================================
__global__ __launch_bounds__(256)
void split_bf16(const float* __restrict__ in,
                __nv_bfloat16* __restrict__ hi, __nv_bfloat16* __restrict__ lo,
                int n)
{
    const int i = (blockIdx.x * 256 + threadIdx.x) * 4;
    if (i >= n) return;
    float4 f4 = *(const float4*)(in + i);
    float f[4] = {f4.x, f4.y, f4.z, f4.w};
    uint16_t h[4], l[4];
#pragma unroll
    for (int j = 0; j < 4; j++) {
        __nv_bfloat16 hb = __float2bfloat16(f[j]);
        __nv_bfloat16 lb = __float2bfloat16(f[j] - __bfloat162float(hb));
        h[j] = __bfloat16_as_ushort(hb);
        l[j] = __bfloat16_as_ushort(lb);
    }
    *(uint2*)(hi + i) = make_uint2((uint32_t)h[0] | ((uint32_t)h[1] << 16),
                                   (uint32_t)h[2] | ((uint32_t)h[3] << 16));
    *(uint2*)(lo + i) = make_uint2((uint32_t)l[0] | ((uint32_t)l[1] << 16),
                                   (uint32_t)l[2] | ((uint32_t)l[3] << 16));
}

// =================================================================
// mma.sync bf16x3 GEMM (pre-split inputs, cp.async double buffer)
// =================================================================
#define SROW 20
#define ARR_W (128 * SROW)
#define BUF_W (4 * ARR_W)
#define GEMM_SMEM (2 * BUF_W * 4)

__global__ __launch_bounds__(256, 2)
void mma_gemm_pre(const __nv_bfloat16* __restrict__ Ahg,
                  const __nv_bfloat16* __restrict__ Alg,
                  const __nv_bfloat16* __restrict__ Bhg,
                  const __nv_bfloat16* __restrict__ Blg,
                  float* __restrict__ C, int M, int N, int K)
{
    extern __shared__ uint32_t sw[];
    const uint32_t sbase = smem_u32(sw);

    const int tid = threadIdx.x;
    const int wid = tid >> 5;
    const int lane = tid & 31;
    const int g = lane >> 2;
    const int tig = lane & 3;
    const int wm = (wid & 1) * 64;
    const int wn = (wid >> 1) * 32;

    const int bm = blockIdx.y * 128;
    const int bn = blockIdx.x * 128;

    const int s0 = tid * 2;
    const int lrow0 = s0 >> 2, lseg0 = s0 & 3;
    const int lrow1 = (s0 + 1) >> 2, lseg1 = (s0 + 1) & 3;

    float acc[4][4][4];
#pragma unroll
    for (int mt = 0; mt < 4; mt++)
#pragma unroll
        for (int nt = 0; nt < 4; nt++)
#pragma unroll
            for (int r = 0; r < 4; r++) acc[mt][nt][r] = 0.0f;

    const int nch = K >> 5;

    auto issue = [&](int ci, int buf) {
        const int kc = ci << 5;
        const uint32_t bb = sbase + buf * (BUF_W * 4);
#pragma unroll
        for (int j = 0; j < 2; j++) {
            const int row = j ? lrow1 : lrow0;
            const int seg = j ? lseg1 : lseg0;
            const size_t goff = (size_t)(bm + row) * K + kc + seg * 8;
            const size_t goffB = (size_t)(bn + row) * K + kc + seg * 8;
            const uint32_t soff = (row * SROW + seg * 4) * 4;
            CP_ASYNC(bb + 0 * ARR_W * 4 + soff, Ahg + goff);
            CP_ASYNC(bb + 1 * ARR_W * 4 + soff, Alg + goff);
            CP_ASYNC(bb + 2 * ARR_W * 4 + soff, Bhg + goffB);
            CP_ASYNC(bb + 3 * ARR_W * 4 + soff, Blg + goffB);
        }
    };

    issue(0, 0); CP_COMMIT();
    issue(1, 1); CP_COMMIT();

    for (int ci = 0; ci < nch; ci++) {
        const int buf = ci & 1;
        CP_WAIT1();
        __syncthreads();

        const uint32_t* Ah = sw + buf * BUF_W;
        const uint32_t* Al = Ah + ARR_W;
        const uint32_t* Bh = Ah + 2 * ARR_W;
        const uint32_t* Bl = Ah + 3 * ARR_W;

#pragma unroll
        for (int ks = 0; ks < 2; ks++) {
            const int kw = ks * 8;
            uint32_t bhf[4][2], blf[4][2];
#pragma unroll
            for (int nt = 0; nt < 4; nt++) {
                const int nb = (wn + nt * 8 + g) * SROW + kw + tig;
                bhf[nt][0] = Bh[nb]; bhf[nt][1] = Bh[nb + 4];
                blf[nt][0] = Bl[nb]; blf[nt][1] = Bl[nb + 4];
            }
#pragma unroll
            for (int mt = 0; mt < 4; mt++) {
                const int ab = (wm + mt * 16 + g) * SROW + kw + tig;
                uint32_t ah[4], al[4];
                ah[0] = Ah[ab];
                ah[1] = Ah[ab + 8 * SROW];
                ah[2] = Ah[ab + 4];
                ah[3] = Ah[ab + 8 * SROW + 4];
                al[0] = Al[ab];
                al[1] = Al[ab + 8 * SROW];
                al[2] = Al[ab + 4];
                al[3] = Al[ab + 8 * SROW + 4];
#pragma unroll
                for (int nt = 0; nt < 4; nt++) {
                    mma16816(acc[mt][nt], ah, bhf[nt]);
                    mma16816(acc[mt][nt], ah, blf[nt]);
                    mma16816(acc[mt][nt], al, bhf[nt]);
                }
            }
        }
        __syncthreads();
        if (ci + 2 < nch) issue(ci + 2, buf);
        CP_COMMIT();
    }

#pragma unroll
    for (int mt = 0; mt < 4; mt++) {
        const int r0 = bm + wm + mt * 16 + g;
#pragma unroll
        for (int nt = 0; nt < 4; nt++) {
            const int col = bn + wn + nt * 8 + tig * 2;
            *(float2*)&C[(size_t)r0 * N + col] =
                make_float2(acc[mt][nt][0], acc[mt][nt][1]);
            *(float2*)&C[(size_t)(r0 + 8) * N + col] =
                make_float2(acc[mt][nt][2], acc[mt][nt][3]);
        }
    }
}

// =================================================================
// Post-process: v-mix, rmsnorm, rotary; q pre-scaled by ATTN_SCALE;
// outputs bf16 hi/lo q,k,v in (B*H, T, D) layout.
// =================================================================
__device__ __forceinline__ void split_store(__nv_bfloat16* H, __nv_bfloat16* L,
                                            size_t o, float f) {
    __nv_bfloat16 hb = __float2bfloat16(f);
    H[o] = hb;
    L[o] = __float2bfloat16(f - __bfloat162float(hb));
}

__global__ __launch_bounds__(256)
void postproc(const float* __restrict__ qkv, const float* __restrict__ ve,
              const float* __restrict__ lambdas,
              __nv_bfloat16* __restrict__ qh, __nv_bfloat16* __restrict__ ql,
              __nv_bfloat16* __restrict__ kh, __nv_bfloat16* __restrict__ kl,
              __nv_bfloat16* __restrict__ vh, __nv_bfloat16* __restrict__ vl)
{
    const int pair = blockIdx.x * 8 + (threadIdx.x >> 5);
    const int l = threadIdx.x & 31;
    const int m = pair >> 4;
    const int h = pair & 15;
    const int t = m & (TT - 1);
    const int b = m >> 11;

    const float* row = qkv + (size_t)m * N_QKV + h * DD;
    float q0 = row[l],          q1 = row[l + 32];
    float k0 = row[CC + l],     k1 = row[CC + l + 32];
    float v0 = row[2 * CC + l], v1 = row[2 * CC + l + 32];

    const float lam0 = lambdas[0], lam1 = lambdas[1];
    const float* verow = ve + (size_t)m * CC + h * DD;
    v0 = lam0 * v0 + lam1 * verow[l];
    v1 = lam0 * v1 + lam1 * verow[l + 32];

    float sq = q0 * q0 + q1 * q1;
    float sk = k0 * k0 + k1 * k1;
#pragma unroll
    for (int o = 16; o; o >>= 1) {
        sq += __shfl_xor_sync(0xffffffffu, sq, o);
        sk += __shfl_xor_sync(0xffffffffu, sk, o);
    }
    float rq = 1.0f / sqrtf(sq * (1.0f / 64.0f) + RMS_EPS);
    float rk = 1.0f / sqrtf(sk * (1.0f / 64.0f) + RMS_EPS);
    q0 *= rq; q1 *= rq;
    k0 *= rk; k1 *= rk;

    float ang = (l < 16) ? (float)exp2(-(10.0 / 15.0) * (double)l) : 0.0f;
    float th = (float)t * ang;
    float s, c;
    sincosf(th, &s, &c);
    float qa = (q0 * c + q1 * s) * ATTN_SCALE;
    float qb_ = (q1 * c - q0 * s) * ATTN_SCALE;
    float ka = k0 * c + k1 * s;
    float kb_ = k1 * c - k0 * s;

    size_t o = ((size_t)(b * HH + h) * TT + t) * DD + l;
    split_store(qh, ql, o,      qa);
    split_store(qh, ql, o + 32, qb_);
    split_store(kh, kl, o,      ka);
    split_store(kh, kl, o + 32, kb_);
    split_store(vh, vl, o,      v0);
    split_store(vh, vl, o + 32, v1);
}

// =================================================================
// V transpose: (B*H, T, D) -> (B*H, D, T), both hi and lo.
// Grid (T/64, B*H), 256 threads, 64x64 tiles.
// =================================================================
__global__ __launch_bounds__(256)
void transpose_v(const __nv_bfloat16* __restrict__ vh,
                 const __nv_bfloat16* __restrict__ vl,
                 __nv_bfloat16* __restrict__ vth,
                 __nv_bfloat16* __restrict__ vtl)
{
    __shared__ uint16_t th[64][65], tl[64][65];
    const int bh = blockIdx.y, tb = blockIdx.x;
    const int r = threadIdx.x >> 2;
    const int cs = (threadIdx.x & 3) * 16;

    const size_t src = ((size_t)bh * TT + tb * 64 + r) * DD + cs;
    const uint32_t* ph = (const uint32_t*)(vh + src);
    const uint32_t* pl = (const uint32_t*)(vl + src);
#pragma unroll
    for (int j = 0; j < 8; j++) {
        uint32_t wh_ = ph[j], wl_ = pl[j];
        th[r][cs + 2 * j] = (uint16_t)(wh_ & 0xffff);
        th[r][cs + 2 * j + 1] = (uint16_t)(wh_ >> 16);
        tl[r][cs + 2 * j] = (uint16_t)(wl_ & 0xffff);
        tl[r][cs + 2 * j + 1] = (uint16_t)(wl_ >> 16);
    }
    __syncthreads();
    const size_t dst = ((size_t)bh * DD + r) * TT + tb * 64 + cs;
    uint32_t* oh = (uint32_t*)(vth + dst);
    uint32_t* ol = (uint32_t*)(vtl + dst);
#pragma unroll
    for (int j = 0; j < 8; j++) {
        oh[j] = (uint32_t)th[cs + 2 * j][r] | ((uint32_t)th[cs + 2 * j + 1][r] << 16);
        ol[j] = (uint32_t)tl[cs + 2 * j][r] | ((uint32_t)tl[cs + 2 * j + 1][r] << 16);
    }
}

// =================================================================
// Tensor-core flash attention (causal, no-max softmax, bf16x3).
// Grid (16, B*H), 256 threads. BQ=128, BKV=64, D=64.
// Smem word layout (uint32):
//   Qh[0..4607], Ql[4608..], KV buffers at 9216 (2 bufs x 9216 w:
//   Kh,Kl,Vth,Vtl each 64 rows x 36 w), Ph@27648, Pl@32256,
//   lpart (float) @36864 (8 warps x 64 rows).
// Row stride 36 words -> conflict-free frag access ((4g+tig)%32).
// =================================================================
#define FL_SROW 36
#define FL_QH 0
#define FL_QL 4608
#define FL_KV 9216
#define FL_PH 27648
#define FL_PL 32256
#define FL_LP 36864
#define FL_SMEM ((36864 + 512) * 4)

__global__ __launch_bounds__(256, 1)
void flash_mma(const __nv_bfloat16* __restrict__ qh, const __nv_bfloat16* __restrict__ ql,
               const __nv_bfloat16* __restrict__ kh, const __nv_bfloat16* __restrict__ kl,
               const __nv_bfloat16* __restrict__ vth, const __nv_bfloat16* __restrict__ vtl,
               __nv_bfloat16* __restrict__ yh, __nv_bfloat16* __restrict__ yl)
{
    extern __shared__ uint32_t sw[];
    const uint32_t sb = smem_u32(sw);
    const int tid = threadIdx.x;
    const int wid = tid >> 5;
    const int lane = tid & 31;
    const int g = lane >> 2;
    const int tig = lane & 3;
    const int bh = blockIdx.y;
    const int qb = (int)gridDim.x - 1 - (int)blockIdx.x;   // heavy first

    const int wmS = (wid & 1) * 64, wnS = (wid >> 1) * 16;
    const int wmP = (wid & 3) * 32, wnP = (wid >> 2) * 32;

    const size_t base = (size_t)bh * TT * DD;

    // ---- Q tile load (cp.async) ----
    {
        const int arr = tid >> 7;        // 0: hi, 1: lo
        const int row = tid & 127;
        const __nv_bfloat16* src = (arr ? ql : qh) + base + ((size_t)(qb * 128 + row)) * 64;
        const uint32_t dst = sb + ((arr ? FL_QL : FL_QH) + row * FL_SROW) * 4;
#pragma unroll
        for (int s = 0; s < 8; s++) CP_ASYNC(dst + s * 16, src + s * 8);
    }

    // KV loader mapping
    const int kvarr = tid >> 6;          // 0:Kh 1:Kl 2:Vth 3:Vtl
    const int kvrow = tid & 63;
    const bool kvisV = kvarr >= 2;
    const __nv_bfloat16* kvbase =
        (kvarr == 0) ? (kh + base) : (kvarr == 1) ? (kl + base)
        : (kvarr == 2) ? (vth + base) : (vtl + base);
    const uint32_t kvdst0 = sb + (FL_KV + (kvarr & 3) * 2304 + kvrow * FL_SROW) * 4;

    auto issueKV = [&](int kb, int buf) {
        const __nv_bfloat16* src = kvisV
            ? (kvbase + (size_t)kvrow * TT + kb * 64)
            : (kvbase + ((size_t)(kb * 64 + kvrow)) * 64);
        const uint32_t dst = kvdst0 + buf * 9216 * 4;
#pragma unroll
        for (int s = 0; s < 8; s++) CP_ASYNC(dst + s * 16, src + s * 8);
    };

    const int nkb = 2 * qb + 2;
    issueKV(0, 0); CP_COMMIT();          // group: Q + KV0
    if (nkb > 1) issueKV(1, 1);
    CP_COMMIT();                          // group: KV1
    CP_WAIT1();                           // Q + KV0 ready
    __syncthreads();

    float O[2][4][4];
    float lp[8];
#pragma unroll
    for (int i = 0; i < 8; i++) lp[i] = 0.0f;
#pragma unroll
    for (int mt = 0; mt < 2; mt++)
#pragma unroll
        for (int nt = 0; nt < 4; nt++)
#pragma unroll
            for (int r = 0; r < 4; r++) O[mt][nt][r] = 0.0f;

    for (int kb = 0; kb < nkb; kb++) {
        const int buf = kb & 1;
        const uint32_t Kh_ = FL_KV + buf * 9216;
        const uint32_t Kl_ = Kh_ + 2304;
        const uint32_t Vh_ = Kh_ + 4608;
        const uint32_t Vl_ = Kh_ + 6912;

        // ---- S = Q K^T (bf16x3) ----
        float S[4][2][4];
#pragma unroll
        for (int mt = 0; mt < 4; mt++)
#pragma unroll
            for (int nt = 0; nt < 2; nt++)
#pragma unroll
                for (int r = 0; r < 4; r++) S[mt][nt][r] = 0.0f;

#pragma unroll
        for (int ks = 0; ks < 4; ks++) {
            uint32_t bhf[2][2], blf[2][2];
#pragma unroll
            for (int nt = 0; nt < 2; nt++) {
                const uint32_t off = (uint32_t)((wnS + nt * 8 + g) * FL_SROW + tig + ks * 8);
                bhf[nt][0] = sw[Kh_ + off]; bhf[nt][1] = sw[Kh_ + off + 4];
                blf[nt][0] = sw[Kl_ + off]; blf[nt][1] = sw[Kl_ + off + 4];
            }
#pragma unroll
            for (int mt = 0; mt < 4; mt++) {
                const uint32_t off = (uint32_t)((wmS + mt * 16 + g) * FL_SROW + tig + ks * 8);
                uint32_t ah[4], al[4];
                ah[0] = sw[FL_QH + off];
                ah[1] = sw[FL_QH + off + 8 * FL_SROW];
                ah[2] = sw[FL_QH + off + 4];
                ah[3] = sw[FL_QH + off + 8 * FL_SROW + 4];
                al[0] = sw[FL_QL + off];
                al[1] = sw[FL_QL + off + 8 * FL_SROW];
                al[2] = sw[FL_QL + off + 4];
                al[3] = sw[FL_QL + off + 8 * FL_SROW + 4];
#pragma unroll
                for (int nt = 0; nt < 2; nt++) {
                    mma16816(S[mt][nt], ah, bhf[nt]);
                    mma16816(S[mt][nt], ah, blf[nt]);
                    mma16816(S[mt][nt], al, bhf[nt]);
                }
            }
        }

        // ---- exp (no max), row-sum partials, write P hi/lo ----
        const bool diag = (kb >= 2 * qb);
#pragma unroll
        for (int mt = 0; mt < 4; mt++) {
            const int r0 = wmS + mt * 16 + g;
#pragma unroll
            for (int nt = 0; nt < 2; nt++) {
                const int c0 = kb * 64 + wnS + nt * 8 + tig * 2;
#pragma unroll
                for (int h2 = 0; h2 < 2; h2++) {
                    const int r = r0 + h2 * 8;
                    const int grow = qb * 128 + r;
                    float s0 = S[mt][nt][h2 * 2 + 0];
                    float s1 = S[mt][nt][h2 * 2 + 1];
                    float p0 = (diag && (c0 > grow)) ? 0.0f : __expf(s0);
                    float p1 = (diag && (c0 + 1 > grow)) ? 0.0f : __expf(s1);
                    lp[mt * 2 + h2] += p0 + p1;
                    __nv_bfloat16 hb0 = __float2bfloat16(p0);
                    __nv_bfloat16 hb1 = __float2bfloat16(p1);
                    const uint32_t hw = (uint32_t)__bfloat16_as_ushort(hb0) |
                                        ((uint32_t)__bfloat16_as_ushort(hb1) << 16);
                    const uint32_t lw = pack_bf16(p0 - __bfloat162float(hb0),
                                                  p1 - __bfloat162float(hb1));
                    const uint32_t off = (uint32_t)(r * FL_SROW + (wnS >> 1) + nt * 4 + tig);
                    sw[FL_PH + off] = hw;
                    sw[FL_PL + off] = lw;
                }
            }
        }
        __syncthreads();

        // ---- O += P V (bf16x3) ----
#pragma unroll
        for (int ks = 0; ks < 4; ks++) {
            uint32_t bvh[4][2], bvl[4][2];
#pragma unroll
            for (int nt = 0; nt < 4; nt++) {
                const uint32_t off = (uint32_t)((wnP + nt * 8 + g) * FL_SROW + tig + ks * 8);
                bvh[nt][0] = sw[Vh_ + off]; bvh[nt][1] = sw[Vh_ + off + 4];
                bvl[nt][0] = sw[Vl_ + off]; bvl[nt][1] = sw[Vl_ + off + 4];
            }
#pragma unroll
            for (int mt = 0; mt < 2; mt++) {
                const uint32_t off = (uint32_t)((wmP + mt * 16 + g) * FL_SROW + tig + ks * 8);
                uint32_t aph[4], apl[4];
                aph[0] = sw[FL_PH + off];
                aph[1] = sw[FL_PH + off + 8 * FL_SROW];
                aph[2] = sw[FL_PH + off + 4];
                aph[3] = sw[FL_PH + off + 8 * FL_SROW + 4];
                apl[0] = sw[FL_PL + off];
                apl[1] = sw[FL_PL + off + 8 * FL_SROW];
                apl[2] = sw[FL_PL + off + 4];
                apl[3] = sw[FL_PL + off + 8 * FL_SROW + 4];
#pragma unroll
                for (int nt = 0; nt < 4; nt++) {
                    mma16816(O[mt][nt], aph, bvh[nt]);
                    mma16816(O[mt][nt], aph, bvl[nt]);
                    mma16816(O[mt][nt], apl, bvh[nt]);
                }
            }
        }
        __syncthreads();                 // PV done; buf and P free
        if (kb + 2 < nkb) issueKV(kb + 2, buf);
        CP_COMMIT();
        CP_WAIT1();                      // tile kb+1 ready
        __syncthreads();
    }

    // ---- row-sum reduce: over tig lanes, stash per warp ----
    float* lpf = (float*)(sw + FL_LP);
#pragma unroll
    for (int i = 0; i < 8; i++) {
        lp[i] += __shfl_xor_sync(0xffffffffu, lp[i], 1);
        lp[i] += __shfl_xor_sync(0xffffffffu, lp[i], 2);
    }
    if (tig == 0) {
#pragma unroll
        for (int mt = 0; mt < 4; mt++) {
            lpf[wid * 64 + mt * 16 + g] = lp[mt * 2];
            lpf[wid * 64 + mt * 16 + g + 8] = lp[mt * 2 + 1];
        }
    }
    __syncthreads();

    // ---- epilogue: O/l -> y bf16 hi/lo, (M, C) layout ----
    const int b = bh >> 4;
    const int h = bh & 15;
#pragma unroll
    for (int mt = 0; mt < 2; mt++) {
#pragma unroll
        for (int h2 = 0; h2 < 2; h2++) {
            const int r = wmP + mt * 16 + g + h2 * 8;
            const int hm = r >> 6, r6 = r & 63;
            const float lsum = lpf[(hm + 0) * 64 + r6] + lpf[(hm + 2) * 64 + r6] +
                               lpf[(hm + 4) * 64 + r6] + lpf[(hm + 6) * 64 + r6];
            const float linv = 1.0f / lsum;
            const int t = qb * 128 + r;
            const size_t rowoff = ((size_t)(b * TT + t)) * CC + h * 64 + wnP;
#pragma unroll
            for (int nt = 0; nt < 4; nt++) {
                float o0 = O[mt][nt][h2 * 2 + 0] * linv;
                float o1 = O[mt][nt][h2 * 2 + 1] * linv;
                __nv_bfloat16 hb0 = __float2bfloat16(o0);
                __nv_bfloat16 hb1 = __float2bfloat16(o1);
                const size_t col = rowoff + nt * 8 + tig * 2;
                *(uint32_t*)(yh + col) = (uint32_t)__bfloat16_as_ushort(hb0) |
                                         ((uint32_t)__bfloat16_as_ushort(hb1) << 16);
                *(uint32_t*)(yl + col) = pack_bf16(o0 - __bfloat162float(hb0),
                                                   o1 - __bfloat162float(hb1));
            }
        }
    }
}

// =================================================================
// launch
// =================================================================
extern "C" void kernel_launch(void* const* d_in, const int* in_sizes, int n_in,
                              void* d_out, int out_size)
{
    const float* x        = (const float*)d_in[0];
    const float* ve       = (const float*)d_in[1];
    const float* qkv_w    = (const float*)d_in[2];
    const float* lambdas  = (const float*)d_in[3];
    const float* c_proj_w = (const float*)d_in[4];
    float* out = (float*)d_out;

    float* qkv_p;
    cudaGetSymbolAddress((void**)&qkv_p, g_qkv);
    __nv_bfloat16 *xh, *xl, *wh, *wl, *yh, *yl, *ph, *pl;
    cudaGetSymbolAddress((void**)&xh, g_xh); cudaGetSymbolAddress((void**)&xl, g_xl);
    cudaGetSymbolAddress((void**)&wh, g_wh); cudaGetSymbolAddress((void**)&wl, g_wl);
    cudaGetSymbolAddress((void**)&yh, g_yh); cudaGetSymbolAddress((void**)&yl, g_yl);
    cudaGetSymbolAddress((void**)&ph, g_ph); cudaGetSymbolAddress((void**)&pl, g_pl);
    __nv_bfloat16 *qh, *ql, *kh, *kl, *vh, *vl, *vth, *vtl;
    cudaGetSymbolAddress((void**)&qh, g_qh); cudaGetSymbolAddress((void**)&ql, g_ql);
    cudaGetSymbolAddress((void**)&kh, g_kh); cudaGetSymbolAddress((void**)&kl, g_kl);
    cudaGetSymbolAddress((void**)&vh, g_vh); cudaGetSymbolAddress((void**)&vl, g_vl);
    cudaGetSymbolAddress((void**)&vth, g_vth); cudaGetSymbolAddress((void**)&vtl, g_vtl);

    cudaFuncSetAttribute(mma_gemm_pre, cudaFuncAttributeMaxDynamicSharedMemorySize, GEMM_SMEM);
    cudaFuncSetAttribute(flash_mma, cudaFuncAttributeMaxDynamicSharedMemorySize, FL_SMEM);

    // 0) pre-split fp32 -> bf16 hi/lo
    split_bf16<<<(MM * CC) / 1024, 256>>>(x, xh, xl, MM * CC);
    split_bf16<<<(N_QKV * CC) / 1024, 256>>>(qkv_w, wh, wl, N_QKV * CC);

    // 1) qkv = x @ qkv_w^T
    mma_gemm_pre<<<dim3(N_QKV / 128, MM / 128), 256, GEMM_SMEM>>>(
        xh, xl, wh, wl, qkv_p, MM, N_QKV, CC);

    // 2) v-mix + rmsnorm + rotary -> bf16 hi/lo (q scaled by ATTN_SCALE)
    postproc<<<(MM * HH) / 8, 256>>>(qkv_p, ve, lambdas, qh, ql, kh, kl, vh, vl);

    // 2b) transpose V to (B*H, D, T)
    transpose_v<<<dim3(TT / 64, BB * HH), 256>>>(vh, vl, vth, vtl);

    // 3) tensor-core causal flash attention -> y bf16 hi/lo
    flash_mma<<<dim3(TT / 128, BB * HH), 256, FL_SMEM>>>(
        qh, ql, kh, kl, vth, vtl, yh, yl);

    // 4) out = y @ c_proj_w^T
    split_bf16<<<(CC * CC) / 1024, 256>>>(c_proj_w, ph, pl, CC * CC);
    mma_gemm_pre<<<dim3(CC / 128, MM / 128), 256, GEMM_SMEM>>>(
        yh, yl, ph, pl, out, MM, CC, CC);
}

// round 9
// speedup vs baseline: 2.3720x; 1.0493x over previous
#include <cuda_runtime.h>
#include <cuda_bf16.h>
#include <math.h>
#include <stdint.h>

// Problem constants
#define BB 4
#define TT 2048
#define CC 1024
#define HH 16
#define DD 64
#define MM (BB * TT)         // 8192
#define N_QKV (3 * CC)       // 3072
#define ATTN_SCALE 0.12f
#define RMS_EPS 1e-6f

// ---------------- device scratch (allocation-free) ----------------
__device__ float g_qkv[(size_t)MM * N_QKV];          // (M, 3C)
__device__ __nv_bfloat16 g_xh[(size_t)MM * CC],     g_xl[(size_t)MM * CC];
__device__ __nv_bfloat16 g_wh[(size_t)N_QKV * CC],  g_wl[(size_t)N_QKV * CC];
__device__ __nv_bfloat16 g_yh[(size_t)MM * CC],     g_yl[(size_t)MM * CC];
__device__ __nv_bfloat16 g_ph[(size_t)CC * CC],     g_pl[(size_t)CC * CC];
#define AHD ((size_t)BB * HH * TT * DD)
__device__ __nv_bfloat16 g_qh[AHD], g_ql[AHD];
__device__ __nv_bfloat16 g_kh[AHD], g_kl[AHD];
__device__ __nv_bfloat16 g_vh[AHD], g_vl[AHD];
__device__ __nv_bfloat16 g_vth[AHD], g_vtl[AHD];

// =================================================================
// common helpers
// =================================================================
__device__ __forceinline__ uint32_t smem_u32(const void* p) {
    uint32_t a;
    asm("{ .reg .u64 t; cvta.to.shared.u64 t, %1; cvt.u32.u64 %0, t; }"
        : "=r"(a) : "l"(p));
    return a;
}

__device__ __forceinline__ void mma16816(float* d, const uint32_t* a, const uint32_t* b) {
    asm volatile(
        "mma.sync.aligned.m16n8k16.row.col.f32.bf16.bf16.f32 "
        "{%0,%1,%2,%3}, {%4,%5,%6,%7}, {%8,%9}, {%0,%1,%2,%3};"
        : "+f"(d[0]), "+f"(d[1]), "+f"(d[2]), "+f"(d[3])
        : "r"(a[0]), "r"(a[1]), "r"(a[2]), "r"(a[3]), "r"(b[0]), "r"(b[1]));
}

#define LDSM_X4(r, addr) \
    asm volatile("ldmatrix.sync.aligned.m8n8.x4.shared.b16 {%0,%1,%2,%3}, [%4];" \
                 : "=r"((r)[0]), "=r"((r)[1]), "=r"((r)[2]), "=r"((r)[3]) : "r"(addr))
#define LDSM_X2(r, addr) \
    asm volatile("ldmatrix.sync.aligned.m8n8.x2.shared.b16 {%0,%1}, [%2];" \
                 : "=r"((r)[0]), "=r"((r)[1]) : "r"(addr))

#define CP_ASYNC(dst, src) \
    asm volatile("cp.async.cg.shared.global [%0], [%1], 16;" \
                 :: "r"(dst), "l"(src) : "memory")
#define CP_COMMIT() asm volatile("cp.async.commit_group;" ::: "memory")
#define CP_WAIT1()  asm volatile("cp.async.wait_group 1;" ::: "memory")

__device__ __forceinline__ uint32_t pack_bf16(float a, float b) {
    __nv_bfloat16 ha = __float2bfloat16(a);
    __nv_bfloat16 hb = __float2bfloat16(b);
    return (uint32_t)__bfloat16_as_ushort(ha) |
           ((uint32_t)__bfloat16_as_ushort(hb) << 16);
}

// =================================================================
// split: fp32 -> bf16 hi + bf16 lo (residual)
// =================================================================
__global__ __launch_bounds__(256)
void split_bf16(const float* __restrict__ in,
                __nv_bfloat16* __restrict__ hi, __nv_bfloat16* __restrict__ lo,
                int n)
{
    const int i = (blockIdx.x * 256 + threadIdx.x) * 4;
    if (i >= n) return;
    float4 f4 = *(const float4*)(in + i);
    float f[4] = {f4.x, f4.y, f4.z, f4.w};
    uint16_t h[4], l[4];
#pragma unroll
    for (int j = 0; j < 4; j++) {
        __nv_bfloat16 hb = __float2bfloat16(f[j]);
        __nv_bfloat16 lb = __float2bfloat16(f[j] - __bfloat162float(hb));
        h[j] = __bfloat16_as_ushort(hb);
        l[j] = __bfloat16_as_ushort(lb);
    }
    *(uint2*)(hi + i) = make_uint2((uint32_t)h[0] | ((uint32_t)h[1] << 16),
                                   (uint32_t)h[2] | ((uint32_t)h[3] << 16));
    *(uint2*)(lo + i) = make_uint2((uint32_t)l[0] | ((uint32_t)l[1] << 16),
                                   (uint32_t)l[2] | ((uint32_t)l[3] << 16));
}

// =================================================================
// mma.sync bf16x3 GEMM (pre-split, cp.async double buffer, ldmatrix)
// =================================================================
#define SROW 20
#define ARR_W (128 * SROW)
#define BUF_W (4 * ARR_W)
#define GEMM_SMEM (2 * BUF_W * 4)

__global__ __launch_bounds__(256, 2)
void mma_gemm_pre(const __nv_bfloat16* __restrict__ Ahg,
                  const __nv_bfloat16* __restrict__ Alg,
                  const __nv_bfloat16* __restrict__ Bhg,
                  const __nv_bfloat16* __restrict__ Blg,
                  float* __restrict__ C, int M, int N, int K)
{
    extern __shared__ uint32_t sw[];
    const uint32_t sbase = smem_u32(sw);

    const int tid = threadIdx.x;
    const int wid = tid >> 5;
    const int lane = tid & 31;
    const int g = lane >> 2;
    const int tig = lane & 3;
    const int wm = (wid & 1) * 64;
    const int wn = (wid >> 1) * 32;

    const int bm = blockIdx.y * 128;
    const int bn = blockIdx.x * 128;

    const int s0 = tid * 2;
    const int lrow0 = s0 >> 2, lseg0 = s0 & 3;
    const int lrow1 = (s0 + 1) >> 2, lseg1 = (s0 + 1) & 3;

    // ldmatrix lane-dependent byte offsets
    const uint32_t a16 = ((uint32_t)((wm + (lane & 15)) * SROW + (lane >> 4) * 4)) * 4;
    const uint32_t b8  = ((uint32_t)((wn + (lane & 7)) * SROW + ((lane >> 3) & 1) * 4)) * 4;

    float acc[4][4][4];
#pragma unroll
    for (int mt = 0; mt < 4; mt++)
#pragma unroll
        for (int nt = 0; nt < 4; nt++)
#pragma unroll
            for (int r = 0; r < 4; r++) acc[mt][nt][r] = 0.0f;

    const int nch = K >> 5;

    auto issue = [&](int ci, int buf) {
        const int kc = ci << 5;
        const uint32_t bb = sbase + buf * (BUF_W * 4);
#pragma unroll
        for (int j = 0; j < 2; j++) {
            const int row = j ? lrow1 : lrow0;
            const int seg = j ? lseg1 : lseg0;
            const size_t goff = (size_t)(bm + row) * K + kc + seg * 8;
            const size_t goffB = (size_t)(bn + row) * K + kc + seg * 8;
            const uint32_t soff = (row * SROW + seg * 4) * 4;
            CP_ASYNC(bb + 0 * ARR_W * 4 + soff, Ahg + goff);
            CP_ASYNC(bb + 1 * ARR_W * 4 + soff, Alg + goff);
            CP_ASYNC(bb + 2 * ARR_W * 4 + soff, Bhg + goffB);
            CP_ASYNC(bb + 3 * ARR_W * 4 + soff, Blg + goffB);
        }
    };

    issue(0, 0); CP_COMMIT();
    issue(1, 1); CP_COMMIT();

    for (int ci = 0; ci < nch; ci++) {
        const int buf = ci & 1;
        CP_WAIT1();
        __syncthreads();

        const uint32_t Ah_b = sbase + buf * (BUF_W * 4);
        const uint32_t Al_b = Ah_b + ARR_W * 4;
        const uint32_t Bh_b = Ah_b + 2 * ARR_W * 4;
        const uint32_t Bl_b = Ah_b + 3 * ARR_W * 4;

#pragma unroll
        for (int ks = 0; ks < 2; ks++) {
            const uint32_t kwb = ks * 32;   // 8 words
            uint32_t bhf[4][2], blf[4][2];
#pragma unroll
            for (int nt = 0; nt < 4; nt++) {
                LDSM_X2(bhf[nt], Bh_b + b8 + nt * (8 * SROW * 4) + kwb);
                LDSM_X2(blf[nt], Bl_b + b8 + nt * (8 * SROW * 4) + kwb);
            }
#pragma unroll
            for (int mt = 0; mt < 4; mt++) {
                uint32_t ah[4], al[4];
                LDSM_X4(ah, Ah_b + a16 + mt * (16 * SROW * 4) + kwb);
                LDSM_X4(al, Al_b + a16 + mt * (16 * SROW * 4) + kwb);
#pragma unroll
                for (int nt = 0; nt < 4; nt++) {
                    mma16816(acc[mt][nt], ah, bhf[nt]);
                    mma16816(acc[mt][nt], ah, blf[nt]);
                    mma16816(acc[mt][nt], al, bhf[nt]);
                }
            }
        }
        __syncthreads();
        if (ci + 2 < nch) issue(ci + 2, buf);
        CP_COMMIT();
    }

#pragma unroll
    for (int mt = 0; mt < 4; mt++) {
        const int r0 = bm + wm + mt * 16 + g;
#pragma unroll
        for (int nt = 0; nt < 4; nt++) {
            const int col = bn + wn + nt * 8 + tig * 2;
            *(float2*)&C[(size_t)r0 * N + col] =
                make_float2(acc[mt][nt][0], acc[mt][nt][1]);
            *(float2*)&C[(size_t)(r0 + 8) * N + col] =
                make_float2(acc[mt][nt][2], acc[mt][nt][3]);
        }
    }
}

// =================================================================
// Post-process: v-mix, rmsnorm, rotary; q pre-scaled by ATTN_SCALE;
// outputs bf16 hi/lo q,k,v in (B*H, T, D) layout.
// =================================================================
__device__ __forceinline__ void split_store(__nv_bfloat16* H, __nv_bfloat16* L,
                                            size_t o, float f) {
    __nv_bfloat16 hb = __float2bfloat16(f);
    H[o] = hb;
    L[o] = __float2bfloat16(f - __bfloat162float(hb));
}

__global__ __launch_bounds__(256)
void postproc(const float* __restrict__ qkv, const float* __restrict__ ve,
              const float* __restrict__ lambdas,
              __nv_bfloat16* __restrict__ qh, __nv_bfloat16* __restrict__ ql,
              __nv_bfloat16* __restrict__ kh, __nv_bfloat16* __restrict__ kl,
              __nv_bfloat16* __restrict__ vh, __nv_bfloat16* __restrict__ vl)
{
    const int pair = blockIdx.x * 8 + (threadIdx.x >> 5);
    const int l = threadIdx.x & 31;
    const int m = pair >> 4;
    const int h = pair & 15;
    const int t = m & (TT - 1);
    const int b = m >> 11;

    const float* row = qkv + (size_t)m * N_QKV + h * DD;
    float q0 = row[l],          q1 = row[l + 32];
    float k0 = row[CC + l],     k1 = row[CC + l + 32];
    float v0 = row[2 * CC + l], v1 = row[2 * CC + l + 32];

    const float lam0 = lambdas[0], lam1 = lambdas[1];
    const float* verow = ve + (size_t)m * CC + h * DD;
    v0 = lam0 * v0 + lam1 * verow[l];
    v1 = lam0 * v1 + lam1 * verow[l + 32];

    float sq = q0 * q0 + q1 * q1;
    float sk = k0 * k0 + k1 * k1;
#pragma unroll
    for (int o = 16; o; o >>= 1) {
        sq += __shfl_xor_sync(0xffffffffu, sq, o);
        sk += __shfl_xor_sync(0xffffffffu, sk, o);
    }
    float rq = 1.0f / sqrtf(sq * (1.0f / 64.0f) + RMS_EPS);
    float rk = 1.0f / sqrtf(sk * (1.0f / 64.0f) + RMS_EPS);
    q0 *= rq; q1 *= rq;
    k0 *= rk; k1 *= rk;

    float ang = (l < 16) ? (float)exp2(-(10.0 / 15.0) * (double)l) : 0.0f;
    float th = (float)t * ang;
    float s, c;
    sincosf(th, &s, &c);
    float qa = (q0 * c + q1 * s) * ATTN_SCALE;
    float qb_ = (q1 * c - q0 * s) * ATTN_SCALE;
    float ka = k0 * c + k1 * s;
    float kb_ = k1 * c - k0 * s;

    size_t o = ((size_t)(b * HH + h) * TT + t) * DD + l;
    split_store(qh, ql, o,      qa);
    split_store(qh, ql, o + 32, qb_);
    split_store(kh, kl, o,      ka);
    split_store(kh, kl, o + 32, kb_);
    split_store(vh, vl, o,      v0);
    split_store(vh, vl, o + 32, v1);
}

// =================================================================
// V transpose: (B*H, T, D) -> (B*H, D, T), both hi and lo.
// =================================================================
__global__ __launch_bounds__(256)
void transpose_v(const __nv_bfloat16* __restrict__ vh,
                 const __nv_bfloat16* __restrict__ vl,
                 __nv_bfloat16* __restrict__ vth,
                 __nv_bfloat16* __restrict__ vtl)
{
    __shared__ uint16_t th[64][65], tl[64][65];
    const int bh = blockIdx.y, tb = blockIdx.x;
    const int r = threadIdx.x >> 2;
    const int cs = (threadIdx.x & 3) * 16;

    const size_t src = ((size_t)bh * TT + tb * 64 + r) * DD + cs;
    const uint32_t* ph = (const uint32_t*)(vh + src);
    const uint32_t* pl = (const uint32_t*)(vl + src);
#pragma unroll
    for (int j = 0; j < 8; j++) {
        uint32_t wh_ = ph[j], wl_ = pl[j];
        th[r][cs + 2 * j] = (uint16_t)(wh_ & 0xffff);
        th[r][cs + 2 * j + 1] = (uint16_t)(wh_ >> 16);
        tl[r][cs + 2 * j] = (uint16_t)(wl_ & 0xffff);
        tl[r][cs + 2 * j + 1] = (uint16_t)(wl_ >> 16);
    }
    __syncthreads();
    const size_t dst = ((size_t)bh * DD + r) * TT + tb * 64 + cs;
    uint32_t* oh = (uint32_t*)(vth + dst);
    uint32_t* ol = (uint32_t*)(vtl + dst);
#pragma unroll
    for (int j = 0; j < 8; j++) {
        oh[j] = (uint32_t)th[cs + 2 * j][r] | ((uint32_t)th[cs + 2 * j + 1][r] << 16);
        ol[j] = (uint32_t)tl[cs + 2 * j][r] | ((uint32_t)tl[cs + 2 * j + 1][r] << 16);
    }
}

// =================================================================
// Tensor-core flash attention (causal, no-max softmax, bf16x3),
// fragments via ldmatrix.
// =================================================================
#define FL_SROW 36
#define FL_QH 0
#define FL_QL 4608
#define FL_KV 9216
#define FL_PH 27648
#define FL_PL 32256
#define FL_LP 36864
#define FL_SMEM ((36864 + 512) * 4)

__global__ __launch_bounds__(256, 1)
void flash_mma(const __nv_bfloat16* __restrict__ qh, const __nv_bfloat16* __restrict__ ql,
               const __nv_bfloat16* __restrict__ kh, const __nv_bfloat16* __restrict__ kl,
               const __nv_bfloat16* __restrict__ vth, const __nv_bfloat16* __restrict__ vtl,
               __nv_bfloat16* __restrict__ yh, __nv_bfloat16* __restrict__ yl)
{
    extern __shared__ uint32_t sw[];
    const uint32_t sb = smem_u32(sw);
    const int tid = threadIdx.x;
    const int wid = tid >> 5;
    const int lane = tid & 31;
    const int g = lane >> 2;
    const int tig = lane & 3;
    const int bh = blockIdx.y;
    const int qb = (int)gridDim.x - 1 - (int)blockIdx.x;   // heavy first

    const int wmS = (wid & 1) * 64, wnS = (wid >> 1) * 16;
    const int wmP = (wid & 3) * 32, wnP = (wid >> 2) * 32;

    // ldmatrix lane-dependent byte offsets (FL_SROW stride)
    const uint32_t a16 = ((uint32_t)(((lane & 15)) * FL_SROW + (lane >> 4) * 4)) * 4;
    const uint32_t b8  = ((uint32_t)(((lane & 7)) * FL_SROW + ((lane >> 3) & 1) * 4)) * 4;

    const size_t base = (size_t)bh * TT * DD;

    // ---- Q tile load (cp.async) ----
    {
        const int arr = tid >> 7;
        const int row = tid & 127;
        const __nv_bfloat16* src = (arr ? ql : qh) + base + ((size_t)(qb * 128 + row)) * 64;
        const uint32_t dst = sb + ((arr ? FL_QL : FL_QH) + row * FL_SROW) * 4;
#pragma unroll
        for (int s = 0; s < 8; s++) CP_ASYNC(dst + s * 16, src + s * 8);
    }

    const int kvarr = tid >> 6;
    const int kvrow = tid & 63;
    const bool kvisV = kvarr >= 2;
    const __nv_bfloat16* kvbase =
        (kvarr == 0) ? (kh + base) : (kvarr == 1) ? (kl + base)
        : (kvarr == 2) ? (vth + base) : (vtl + base);
    const uint32_t kvdst0 = sb + (FL_KV + (kvarr & 3) * 2304 + kvrow * FL_SROW) * 4;

    auto issueKV = [&](int kb, int buf) {
        const __nv_bfloat16* src = kvisV
            ? (kvbase + (size_t)kvrow * TT + kb * 64)
            : (kvbase + ((size_t)(kb * 64 + kvrow)) * 64);
        const uint32_t dst = kvdst0 + buf * 9216 * 4;
#pragma unroll
        for (int s = 0; s < 8; s++) CP_ASYNC(dst + s * 16, src + s * 8);
    };

    const int nkb = 2 * qb + 2;
    issueKV(0, 0); CP_COMMIT();
    if (nkb > 1) issueKV(1, 1);
    CP_COMMIT();
    CP_WAIT1();
    __syncthreads();

    float O[2][4][4];
    float lp[8];
#pragma unroll
    for (int i = 0; i < 8; i++) lp[i] = 0.0f;
#pragma unroll
    for (int mt = 0; mt < 2; mt++)
#pragma unroll
        for (int nt = 0; nt < 4; nt++)
#pragma unroll
            for (int r = 0; r < 4; r++) O[mt][nt][r] = 0.0f;

    for (int kb = 0; kb < nkb; kb++) {
        const int buf = kb & 1;
        const uint32_t Khb = sb + (FL_KV + buf * 9216) * 4;
        const uint32_t Klb = Khb + 2304 * 4;
        const uint32_t Vhb = Khb + 4608 * 4;
        const uint32_t Vlb = Khb + 6912 * 4;

        // ---- S = Q K^T (bf16x3, ldmatrix) ----
        float S[4][2][4];
#pragma unroll
        for (int mt = 0; mt < 4; mt++)
#pragma unroll
            for (int nt = 0; nt < 2; nt++)
#pragma unroll
                for (int r = 0; r < 4; r++) S[mt][nt][r] = 0.0f;

#pragma unroll
        for (int ks = 0; ks < 4; ks++) {
            const uint32_t kwb = ks * 32;
            uint32_t bhf[2][2], blf[2][2];
#pragma unroll
            for (int nt = 0; nt < 2; nt++) {
                LDSM_X2(bhf[nt], Khb + b8 + (wnS + nt * 8) * (FL_SROW * 4) + kwb);
                LDSM_X2(blf[nt], Klb + b8 + (wnS + nt * 8) * (FL_SROW * 4) + kwb);
            }
#pragma unroll
            for (int mt = 0; mt < 4; mt++) {
                uint32_t ah[4], al[4];
                LDSM_X4(ah, sb + FL_QH * 4 + a16 + (wmS + mt * 16) * (FL_SROW * 4) + kwb);
                LDSM_X4(al, sb + FL_QL * 4 + a16 + (wmS + mt * 16) * (FL_SROW * 4) + kwb);
#pragma unroll
                for (int nt = 0; nt < 2; nt++) {
                    mma16816(S[mt][nt], ah, bhf[nt]);
                    mma16816(S[mt][nt], ah, blf[nt]);
                    mma16816(S[mt][nt], al, bhf[nt]);
                }
            }
        }

        // ---- exp (no max), row-sum partials, write P hi/lo ----
        const bool diag = (kb >= 2 * qb);
#pragma unroll
        for (int mt = 0; mt < 4; mt++) {
            const int r0 = wmS + mt * 16 + g;
#pragma unroll
            for (int nt = 0; nt < 2; nt++) {
                const int c0 = kb * 64 + wnS + nt * 8 + tig * 2;
#pragma unroll
                for (int h2 = 0; h2 < 2; h2++) {
                    const int r = r0 + h2 * 8;
                    const int grow = qb * 128 + r;
                    float s0 = S[mt][nt][h2 * 2 + 0];
                    float s1 = S[mt][nt][h2 * 2 + 1];
                    float p0 = (diag && (c0 > grow)) ? 0.0f : __expf(s0);
                    float p1 = (diag && (c0 + 1 > grow)) ? 0.0f : __expf(s1);
                    lp[mt * 2 + h2] += p0 + p1;
                    __nv_bfloat16 hb0 = __float2bfloat16(p0);
                    __nv_bfloat16 hb1 = __float2bfloat16(p1);
                    const uint32_t hw = (uint32_t)__bfloat16_as_ushort(hb0) |
                                        ((uint32_t)__bfloat16_as_ushort(hb1) << 16);
                    const uint32_t lw = pack_bf16(p0 - __bfloat162float(hb0),
                                                  p1 - __bfloat162float(hb1));
                    const uint32_t off = (uint32_t)(r * FL_SROW + (wnS >> 1) + nt * 4 + tig);
                    sw[FL_PH + off] = hw;
                    sw[FL_PL + off] = lw;
                }
            }
        }
        __syncthreads();

        // ---- O += P V (bf16x3, ldmatrix) ----
#pragma unroll
        for (int ks = 0; ks < 4; ks++) {
            const uint32_t kwb = ks * 32;
            uint32_t bvh[4][2], bvl[4][2];
#pragma unroll
            for (int nt = 0; nt < 4; nt++) {
                LDSM_X2(bvh[nt], Vhb + b8 + (wnP + nt * 8) * (FL_SROW * 4) + kwb);
                LDSM_X2(bvl[nt], Vlb + b8 + (wnP + nt * 8) * (FL_SROW * 4) + kwb);
            }
#pragma unroll
            for (int mt = 0; mt < 2; mt++) {
                uint32_t aph[4], apl[4];
                LDSM_X4(aph, sb + FL_PH * 4 + a16 + (wmP + mt * 16) * (FL_SROW * 4) + kwb);
                LDSM_X4(apl, sb + FL_PL * 4 + a16 + (wmP + mt * 16) * (FL_SROW * 4) + kwb);
#pragma unroll
                for (int nt = 0; nt < 4; nt++) {
                    mma16816(O[mt][nt], aph, bvh[nt]);
                    mma16816(O[mt][nt], aph, bvl[nt]);
                    mma16816(O[mt][nt], apl, bvh[nt]);
                }
            }
        }
        __syncthreads();
        if (kb + 2 < nkb) issueKV(kb + 2, buf);
        CP_COMMIT();
        CP_WAIT1();
        __syncthreads();
    }

    // ---- row-sum reduce ----
    float* lpf = (float*)(sw + FL_LP);
#pragma unroll
    for (int i = 0; i < 8; i++) {
        lp[i] += __shfl_xor_sync(0xffffffffu, lp[i], 1);
        lp[i] += __shfl_xor_sync(0xffffffffu, lp[i], 2);
    }
    if (tig == 0) {
#pragma unroll
        for (int mt = 0; mt < 4; mt++) {
            lpf[wid * 64 + mt * 16 + g] = lp[mt * 2];
            lpf[wid * 64 + mt * 16 + g + 8] = lp[mt * 2 + 1];
        }
    }
    __syncthreads();

    // ---- epilogue ----
    const int b = bh >> 4;
    const int h = bh & 15;
#pragma unroll
    for (int mt = 0; mt < 2; mt++) {
#pragma unroll
        for (int h2 = 0; h2 < 2; h2++) {
            const int r = wmP + mt * 16 + g + h2 * 8;
            const int hm = r >> 6, r6 = r & 63;
            const float lsum = lpf[(hm + 0) * 64 + r6] + lpf[(hm + 2) * 64 + r6] +
                               lpf[(hm + 4) * 64 + r6] + lpf[(hm + 6) * 64 + r6];
            const float linv = 1.0f / lsum;
            const int t = qb * 128 + r;
            const size_t rowoff = ((size_t)(b * TT + t)) * CC + h * 64 + wnP;
#pragma unroll
            for (int nt = 0; nt < 4; nt++) {
                float o0 = O[mt][nt][h2 * 2 + 0] * linv;
                float o1 = O[mt][nt][h2 * 2 + 1] * linv;
                __nv_bfloat16 hb0 = __float2bfloat16(o0);
                __nv_bfloat16 hb1 = __float2bfloat16(o1);
                const size_t col = rowoff + nt * 8 + tig * 2;
                *(uint32_t*)(yh + col) = (uint32_t)__bfloat16_as_ushort(hb0) |
                                         ((uint32_t)__bfloat16_as_ushort(hb1) << 16);
                *(uint32_t*)(yl + col) = pack_bf16(o0 - __bfloat162float(hb0),
                                                   o1 - __bfloat162float(hb1));
            }
        }
    }
}

// =================================================================
// launch
// =================================================================
extern "C" void kernel_launch(void* const* d_in, const int* in_sizes, int n_in,
                              void* d_out, int out_size)
{
    const float* x        = (const float*)d_in[0];
    const float* ve       = (const float*)d_in[1];
    const float* qkv_w    = (const float*)d_in[2];
    const float* lambdas  = (const float*)d_in[3];
    const float* c_proj_w = (const float*)d_in[4];
    float* out = (float*)d_out;

    float* qkv_p;
    cudaGetSymbolAddress((void**)&qkv_p, g_qkv);
    __nv_bfloat16 *xh, *xl, *wh, *wl, *yh, *yl, *ph, *pl;
    cudaGetSymbolAddress((void**)&xh, g_xh); cudaGetSymbolAddress((void**)&xl, g_xl);
    cudaGetSymbolAddress((void**)&wh, g_wh); cudaGetSymbolAddress((void**)&wl, g_wl);
    cudaGetSymbolAddress((void**)&yh, g_yh); cudaGetSymbolAddress((void**)&yl, g_yl);
    cudaGetSymbolAddress((void**)&ph, g_ph); cudaGetSymbolAddress((void**)&pl, g_pl);
    __nv_bfloat16 *qh, *ql, *kh, *kl, *vh, *vl, *vth, *vtl;
    cudaGetSymbolAddress((void**)&qh, g_qh); cudaGetSymbolAddress((void**)&ql, g_ql);
    cudaGetSymbolAddress((void**)&kh, g_kh); cudaGetSymbolAddress((void**)&kl, g_kl);
    cudaGetSymbolAddress((void**)&vh, g_vh); cudaGetSymbolAddress((void**)&vl, g_vl);
    cudaGetSymbolAddress((void**)&vth, g_vth); cudaGetSymbolAddress((void**)&vtl, g_vtl);

    cudaFuncSetAttribute(mma_gemm_pre, cudaFuncAttributeMaxDynamicSharedMemorySize, GEMM_SMEM);
    cudaFuncSetAttribute(flash_mma, cudaFuncAttributeMaxDynamicSharedMemorySize, FL_SMEM);

    // 0) pre-split fp32 -> bf16 hi/lo
    split_bf16<<<(MM * CC) / 1024, 256>>>(x, xh, xl, MM * CC);
    split_bf16<<<(N_QKV * CC) / 1024, 256>>>(qkv_w, wh, wl, N_QKV * CC);

    // 1) qkv = x @ qkv_w^T
    mma_gemm_pre<<<dim3(N_QKV / 128, MM / 128), 256, GEMM_SMEM>>>(
        xh, xl, wh, wl, qkv_p, MM, N_QKV, CC);

    // 2) v-mix + rmsnorm + rotary -> bf16 hi/lo (q scaled by ATTN_SCALE)
    postproc<<<(MM * HH) / 8, 256>>>(qkv_p, ve, lambdas, qh, ql, kh, kl, vh, vl);

    // 2b) transpose V to (B*H, D, T)
    transpose_v<<<dim3(TT / 64, BB * HH), 256>>>(vh, vl, vth, vtl);

    // 3) tensor-core causal flash attention -> y bf16 hi/lo
    flash_mma<<<dim3(TT / 128, BB * HH), 256, FL_SMEM>>>(
        qh, ql, kh, kl, vth, vtl, yh, yl);

    // 4) out = y @ c_proj_w^T
    split_bf16<<<(CC * CC) / 1024, 256>>>(c_proj_w, ph, pl, CC * CC);
    mma_gemm_pre<<<dim3(CC / 128, MM / 128), 256, GEMM_SMEM>>>(
        yh, yl, ph, pl, out, MM, CC, CC);
}